// round 1
// baseline (speedup 1.0000x reference)
#include <cuda_runtime.h>
#include <math.h>

#define Bdim 2
#define Tdim 2048
#define Cdim 1024
#define Hdim 16
#define Sdim 16
#define HDdim 64
#define Mrows (Bdim*Tdim)   /* 4096 */

// ---------------- device scratch (static, no allocation) ----------------
__device__ float g_xbase[Mrows*Cdim];
__device__ float g_delta[Mrows*Cdim];
__device__ float g_Bmat [Mrows*Sdim];
__device__ float g_Cmat [Mrows*Sdim];
__device__ float g_y    [Mrows*Cdim];
__device__ float g_hyb  [Mrows*Cdim];
__device__ float g_q    [Mrows*Cdim];
__device__ float g_k    [Mrows*Cdim];
__device__ float g_v    [Mrows*Cdim];
__device__ float g_ao   [Mrows*Cdim];

// ---------------- SGEMM: out = act(A @ W + bias) ----------------
// A: MxK row-major, W: KxN row-major. MODE 0: plain store. MODE 1: softplus.
// MODE 2: store into (B,H,T,HD) layout for attention heads.
// BM=BN=128, BK=8, 256 threads, 8x8 microtile split into 2x2 float4 quads.
template<int MODE>
__global__ __launch_bounds__(256, 2)
void sgemm_kernel(const float* __restrict__ A, const float* __restrict__ W,
                  const float* __restrict__ bias, float* __restrict__ out,
                  int M, int N, int K)
{
    __shared__ float As[8][128];
    __shared__ float Bs[8][128];
    const int tid  = threadIdx.x;
    const int row0 = blockIdx.y * 128;
    const int col0 = blockIdx.x * 128;
    const int arow = tid >> 1;
    const int ak   = (tid & 1) << 2;
    const int brow = tid >> 5;
    const int bcol = (tid & 31) << 2;
    const int tr   = (tid >> 4) << 2;   // 0..60
    const int tc   = (tid & 15) << 2;   // 0..60

    float acc[8][8];
#pragma unroll
    for (int i = 0; i < 8; i++)
#pragma unroll
        for (int j = 0; j < 8; j++) acc[i][j] = 0.f;

    const float* Ap = A + (size_t)(row0 + arow) * K + ak;
    const float* Wp = W + (size_t)brow * N + col0 + bcol;

    for (int k0 = 0; k0 < K; k0 += 8) {
        float4 a4 = *(const float4*)(Ap + k0);
        float4 b4 = *(const float4*)(Wp + (size_t)k0 * N);
        As[ak + 0][arow] = a4.x;
        As[ak + 1][arow] = a4.y;
        As[ak + 2][arow] = a4.z;
        As[ak + 3][arow] = a4.w;
        *(float4*)&Bs[brow][bcol] = b4;
        __syncthreads();
#pragma unroll
        for (int k = 0; k < 8; k++) {
            float4 a0 = *(const float4*)&As[k][tr];
            float4 a1 = *(const float4*)&As[k][tr + 64];
            float4 b0 = *(const float4*)&Bs[k][tc];
            float4 b1 = *(const float4*)&Bs[k][tc + 64];
            float ar[8] = {a0.x,a0.y,a0.z,a0.w,a1.x,a1.y,a1.z,a1.w};
            float br[8] = {b0.x,b0.y,b0.z,b0.w,b1.x,b1.y,b1.z,b1.w};
#pragma unroll
            for (int i = 0; i < 8; i++)
#pragma unroll
                for (int j = 0; j < 8; j++)
                    acc[i][j] = fmaf(ar[i], br[j], acc[i][j]);
        }
        __syncthreads();
    }

#pragma unroll
    for (int ih = 0; ih < 2; ih++) {
#pragma unroll
        for (int i = 0; i < 4; i++) {
            int r = row0 + ih * 64 + tr + i;
#pragma unroll
            for (int jh = 0; jh < 2; jh++) {
                int cb = col0 + jh * 64 + tc;
                float4 bv = *(const float4*)(bias + cb);
                float4 vv;
                vv.x = acc[ih*4+i][jh*4+0] + bv.x;
                vv.y = acc[ih*4+i][jh*4+1] + bv.y;
                vv.z = acc[ih*4+i][jh*4+2] + bv.z;
                vv.w = acc[ih*4+i][jh*4+3] + bv.w;
                if (MODE == 1) {  // softplus
                    vv.x = (vv.x > 20.f) ? vv.x : log1pf(expf(vv.x));
                    vv.y = (vv.y > 20.f) ? vv.y : log1pf(expf(vv.y));
                    vv.z = (vv.z > 20.f) ? vv.z : log1pf(expf(vv.z));
                    vv.w = (vv.w > 20.f) ? vv.w : log1pf(expf(vv.w));
                }
                if (MODE == 2) {
                    int b = r >> 11, t = r & (Tdim - 1);
                    int h = cb >> 6, d = cb & 63;
                    float* dst = out + (((size_t)(b * Hdim + h) * Tdim + t) << 6) + d;
                    *(float4*)dst = vv;
                } else {
                    *(float4*)(out + (size_t)r * N + cb) = vv;
                }
            }
        }
    }
}

// ---------------- skinny GEMM: Bm = x@WB, Cm = x@WC (N=16) ----------------
__global__ __launch_bounds__(256)
void skinny_kernel(const float* __restrict__ x, const float* __restrict__ WB,
                   const float* __restrict__ WC,
                   float* __restrict__ Bm, float* __restrict__ Cm)
{
    __shared__ float wb[128 * 16];
    __shared__ float wc[128 * 16];
    __shared__ float xs[16][128];
    const int tid = threadIdx.x;
    const int m0  = blockIdx.x * 16;
    const int rl  = tid >> 4;
    const int s   = tid & 15;
    float accB = 0.f, accC = 0.f;

    for (int k0 = 0; k0 < Cdim; k0 += 128) {
#pragma unroll
        for (int u = 0; u < 2; u++) {
            int idx = tid * 8 + u * 4;
            *(float4*)&wb[idx] = *(const float4*)(WB + k0 * 16 + idx);
            *(float4*)&wc[idx] = *(const float4*)(WC + k0 * 16 + idx);
        }
        {
            int row = tid >> 4;
            int cc  = (tid & 15) * 8;
            const float* xp = x + (size_t)(m0 + row) * Cdim + k0 + cc;
            *(float4*)&xs[row][cc]     = *(const float4*)(xp);
            *(float4*)&xs[row][cc + 4] = *(const float4*)(xp + 4);
        }
        __syncthreads();
#pragma unroll 8
        for (int kk = 0; kk < 128; kk++) {
            float xv = xs[rl][kk];
            accB = fmaf(xv, wb[kk * 16 + s], accB);
            accC = fmaf(xv, wc[kk * 16 + s], accC);
        }
        __syncthreads();
    }
    Bm[(size_t)(m0 + rl) * 16 + s] = accB;
    Cm[(size_t)(m0 + rl) * 16 + s] = accC;
}

// ---------------- SSM scan: one thread per (b,c,s), shfl-reduce over s ----
__global__ __launch_bounds__(256)
void scan_kernel(const float* __restrict__ A_log,
                 const float* __restrict__ delta,
                 const float* __restrict__ xb,
                 const float* __restrict__ Bm,
                 const float* __restrict__ Cm,
                 float* __restrict__ y)
{
    const int gid = blockIdx.x * 256 + threadIdx.x;
    const int s   = gid & 15;
    const int c   = (gid >> 4) & (Cdim - 1);
    const int b   = gid >> 14;
    const float LOG2E = 1.4426950408889634f;
    const float a2 = -expf(A_log[c * Sdim + s]) * LOG2E;

    const float* dp = delta + (size_t)b * Tdim * Cdim + c;
    const float* xp = xb    + (size_t)b * Tdim * Cdim + c;
    const float* bp = Bm    + (size_t)b * Tdim * Sdim + s;
    const float* cp = Cm    + (size_t)b * Tdim * Sdim + s;
    float*       yp = y     + (size_t)b * Tdim * Cdim + c;

    float h = 0.f;
    float d0 = dp[0], x0 = xp[0], b0 = bp[0], c0 = cp[0];
    for (int t = 0; t < Tdim; t++) {
        float d1 = 0.f, x1 = 0.f, b1 = 0.f, c1 = 0.f;
        if (t + 1 < Tdim) {
            d1 = dp[(t + 1) * Cdim];
            x1 = xp[(t + 1) * Cdim];
            b1 = bp[(t + 1) * Sdim];
            c1 = cp[(t + 1) * Sdim];
        }
        float e = exp2f(d0 * a2);                // = exp(delta * A)
        h = fmaf(e, h, d0 * x0 * b0);
        float p = h * c0;
        p += __shfl_xor_sync(0xffffffffu, p, 8);
        p += __shfl_xor_sync(0xffffffffu, p, 4);
        p += __shfl_xor_sync(0xffffffffu, p, 2);
        p += __shfl_xor_sync(0xffffffffu, p, 1);
        if (s == 0) yp[t * Cdim] = p;
        d0 = d1; x0 = x1; b0 = b1; c0 = c1;
    }
}

// ---------------- add + LayerNorm ----------------
__global__ __launch_bounds__(256)
void addln_kernel(const float* __restrict__ xb, const float* __restrict__ y,
                  const float* __restrict__ gam, const float* __restrict__ bet,
                  float* __restrict__ out)
{
    __shared__ float red[16];
    const int row = blockIdx.x, tid = threadIdx.x;
    const float* p1 = xb + (size_t)row * Cdim;
    const float* p2 = y  + (size_t)row * Cdim;
    float v[4]; float s = 0.f, s2 = 0.f;
#pragma unroll
    for (int i = 0; i < 4; i++) {
        int idx = tid + i * 256;
        v[i] = p1[idx] + p2[idx];
        s += v[i]; s2 += v[i] * v[i];
    }
#pragma unroll
    for (int o = 16; o; o >>= 1) {
        s  += __shfl_xor_sync(0xffffffffu, s,  o);
        s2 += __shfl_xor_sync(0xffffffffu, s2, o);
    }
    if ((tid & 31) == 0) { red[tid >> 5] = s; red[(tid >> 5) + 8] = s2; }
    __syncthreads();
    float S = 0.f, S2 = 0.f;
#pragma unroll
    for (int w = 0; w < 8; w++) { S += red[w]; S2 += red[w + 8]; }
    float mean = S * (1.f / Cdim);
    float var  = S2 * (1.f / Cdim) - mean * mean;
    float rs   = rsqrtf(var + 1e-5f);
#pragma unroll
    for (int i = 0; i < 4; i++) {
        int idx = tid + i * 256;
        out[(size_t)row * Cdim + idx] = (v[i] - mean) * rs * gam[idx] + bet[idx];
    }
}

// ---------------- causal flash attention, fp32, 64x64 tiles --------------
#define FPAD 68
__global__ __launch_bounds__(256)
void flash_kernel(const float* __restrict__ q, const float* __restrict__ k,
                  const float* __restrict__ v, const float* __restrict__ temp,
                  float* __restrict__ out)
{
    extern __shared__ float sm[];
    float* Qt   = sm;                  // [d][r]  64xFPAD
    float* Kt   = Qt + 64 * FPAD;      // [d][c]
    float* Vs   = Kt + 64 * FPAD;      // [kv][d]
    float* St   = Vs + 64 * FPAD;      // [c(kv)][r]
    float* mrow = St + 64 * FPAD;
    float* lrow = mrow + 64;
    float* arow = lrow + 64;

    const int tid = threadIdx.x;
    const int qt = blockIdx.x, h = blockIdx.y, b = blockIdx.z;
    const int bh = b * Hdim + h;
    const float* qb = q + ((size_t)bh * Tdim + qt * 64) * HDdim;
    const float* kb = k + (size_t)bh * Tdim * HDdim;
    const float* vb = v + (size_t)bh * Tdim * HDdim;

    float tv = temp[h];
    float sp = (tv > 20.f) ? tv : log1pf(expf(tv));
    float sc = sp * (1.4426950408889634f / 8.0f);   // softplus(temp)/sqrt(64) * log2e

    {   // load Q transposed (d-major) with prescale
        int r  = tid >> 2;
        int d4 = (tid & 3) * 16;
#pragma unroll
        for (int u = 0; u < 4; u++) {
            float4 qv = *(const float4*)(qb + r * 64 + d4 + u * 4);
            Qt[(d4 + u*4 + 0) * FPAD + r] = qv.x * sc;
            Qt[(d4 + u*4 + 1) * FPAD + r] = qv.y * sc;
            Qt[(d4 + u*4 + 2) * FPAD + r] = qv.z * sc;
            Qt[(d4 + u*4 + 3) * FPAD + r] = qv.w * sc;
        }
    }
    if (tid < 64) { mrow[tid] = -1e30f; lrow[tid] = 0.f; }

    const int tr = (tid >> 4) * 4;
    const int tc = (tid & 15) * 4;
    float o[4][4] = {};

    for (int j = 0; j <= qt; j++) {
        __syncthreads();
        {   // load K transposed + V direct
            int r  = tid >> 2;
            int d4 = (tid & 3) * 16;
            const float* kr = kb + ((size_t)j * 64 + r) * 64 + d4;
            const float* vr = vb + ((size_t)j * 64 + r) * 64 + d4;
#pragma unroll
            for (int u = 0; u < 4; u++) {
                float4 k4 = *(const float4*)(kr + u * 4);
                Kt[(d4 + u*4 + 0) * FPAD + r] = k4.x;
                Kt[(d4 + u*4 + 1) * FPAD + r] = k4.y;
                Kt[(d4 + u*4 + 2) * FPAD + r] = k4.z;
                Kt[(d4 + u*4 + 3) * FPAD + r] = k4.w;
                *(float4*)&Vs[r * FPAD + d4 + u * 4] = *(const float4*)(vr + u * 4);
            }
        }
        __syncthreads();

        // S = Q @ K^T (pre-scaled, log2 domain)
        float sacc[4][4] = {};
#pragma unroll 8
        for (int kk = 0; kk < 64; kk++) {
            float4 qv = *(const float4*)&Qt[kk * FPAD + tr];
            float4 kv4 = *(const float4*)&Kt[kk * FPAD + tc];
            float qa[4] = {qv.x, qv.y, qv.z, qv.w};
            float ka[4] = {kv4.x, kv4.y, kv4.z, kv4.w};
#pragma unroll
            for (int i = 0; i < 4; i++)
#pragma unroll
                for (int jj = 0; jj < 4; jj++)
                    sacc[i][jj] = fmaf(qa[i], ka[jj], sacc[i][jj]);
        }
        const bool diag = (j == qt);
#pragma unroll
        for (int i = 0; i < 4; i++)
#pragma unroll
            for (int jj = 0; jj < 4; jj++) {
                float val = sacc[i][jj];
                if (diag && (tc + jj > tr + i)) val = -1e30f;
                St[(tc + jj) * FPAD + (tr + i)] = val;
            }
        __syncthreads();

        {   // online softmax (4 threads per row)
            int row = tid >> 2, seg = tid & 3;
            float mx = -1e30f;
#pragma unroll
            for (int i = 0; i < 16; i++)
                mx = fmaxf(mx, St[(seg * 16 + i) * FPAD + row]);
            mx = fmaxf(mx, __shfl_xor_sync(0xffffffffu, mx, 1));
            mx = fmaxf(mx, __shfl_xor_sync(0xffffffffu, mx, 2));
            float mold = mrow[row];
            float mnew = fmaxf(mold, mx);
            float al   = exp2f(mold - mnew);
            float ssum = 0.f;
#pragma unroll
            for (int i = 0; i < 16; i++) {
                float p = exp2f(St[(seg * 16 + i) * FPAD + row] - mnew);
                St[(seg * 16 + i) * FPAD + row] = p;
                ssum += p;
            }
            ssum += __shfl_xor_sync(0xffffffffu, ssum, 1);
            ssum += __shfl_xor_sync(0xffffffffu, ssum, 2);
            if (seg == 0) {
                mrow[row] = mnew;
                arow[row] = al;
                lrow[row] = lrow[row] * al + ssum;
            }
        }
        __syncthreads();

        // rescale O, then O += P @ V
#pragma unroll
        for (int i = 0; i < 4; i++) {
            float al = arow[tr + i];
#pragma unroll
            for (int jj = 0; jj < 4; jj++) o[i][jj] *= al;
        }
#pragma unroll 8
        for (int kk = 0; kk < 64; kk++) {
            float4 pv = *(const float4*)&St[kk * FPAD + tr];
            float4 vv4 = *(const float4*)&Vs[kk * FPAD + tc];
            float pa[4] = {pv.x, pv.y, pv.z, pv.w};
            float va[4] = {vv4.x, vv4.y, vv4.z, vv4.w};
#pragma unroll
            for (int i = 0; i < 4; i++)
#pragma unroll
                for (int jj = 0; jj < 4; jj++)
                    o[i][jj] = fmaf(pa[i], va[jj], o[i][jj]);
        }
    }

    // write out: (B,T,C) with c = h*64 + d
#pragma unroll
    for (int i = 0; i < 4; i++) {
        int r = tr + i;
        float linv = 1.0f / lrow[r];
        float4 vo;
        vo.x = o[i][0] * linv; vo.y = o[i][1] * linv;
        vo.z = o[i][2] * linv; vo.w = o[i][3] * linv;
        size_t dst = ((size_t)b * Tdim + (size_t)qt * 64 + r) * Cdim + h * HDdim + tc;
        *(float4*)(out + dst) = vo;
    }
}

// ---------------- host ----------------
static float* symaddr(const void* s) {
    void* p = nullptr;
    cudaGetSymbolAddress(&p, s);
    return (float*)p;
}

extern "C" void kernel_launch(void* const* d_in, const int* in_sizes, int n_in,
                              void* d_out, int out_size)
{
    const float* x     = (const float*)d_in[0];
    const float* A_log = (const float*)d_in[1];
    const float* Wd    = (const float*)d_in[2];
    const float* bd    = (const float*)d_in[3];
    const float* WB    = (const float*)d_in[4];
    const float* WC    = (const float*)d_in[5];
    const float* Wq    = (const float*)d_in[6];
    const float* bq    = (const float*)d_in[7];
    const float* Wk    = (const float*)d_in[8];
    const float* bk    = (const float*)d_in[9];
    const float* Wv    = (const float*)d_in[10];
    const float* bv    = (const float*)d_in[11];
    const float* Wx    = (const float*)d_in[12];
    const float* bx    = (const float*)d_in[13];
    const float* Wo    = (const float*)d_in[14];
    const float* bo    = (const float*)d_in[15];
    const float* lng   = (const float*)d_in[16];
    const float* lnb   = (const float*)d_in[17];
    const float* temp  = (const float*)d_in[18];
    float* out = (float*)d_out;

    float* xbase = symaddr(g_xbase);
    float* delta = symaddr(g_delta);
    float* Bm    = symaddr(g_Bmat);
    float* Cm    = symaddr(g_Cmat);
    float* y     = symaddr(g_y);
    float* hyb   = symaddr(g_hyb);
    float* q     = symaddr(g_q);
    float* k     = symaddr(g_k);
    float* v     = symaddr(g_v);
    float* ao    = symaddr(g_ao);

    dim3 gg(Cdim / 128, Mrows / 128);   // (8, 32)

    sgemm_kernel<0><<<gg, 256>>>(x, Wx, bx, xbase, Mrows, Cdim, Cdim);
    sgemm_kernel<1><<<gg, 256>>>(x, Wd, bd, delta, Mrows, Cdim, Cdim);
    skinny_kernel<<<Mrows / 16, 256>>>(x, WB, WC, Bm, Cm);
    scan_kernel<<<(Bdim * Cdim * Sdim) / 256, 256>>>(A_log, delta, xbase, Bm, Cm, y);
    addln_kernel<<<Mrows, 256>>>(xbase, y, lng, lnb, hyb);
    sgemm_kernel<2><<<gg, 256>>>(hyb, Wq, bq, q, Mrows, Cdim, Cdim);
    sgemm_kernel<2><<<gg, 256>>>(hyb, Wk, bk, k, Mrows, Cdim, Cdim);
    sgemm_kernel<2><<<gg, 256>>>(hyb, Wv, bv, v, Mrows, Cdim, Cdim);

    const int flash_smem = (4 * 64 * FPAD + 3 * 64) * (int)sizeof(float);  // 70400 B
    cudaFuncSetAttribute(flash_kernel, cudaFuncAttributeMaxDynamicSharedMemorySize, flash_smem);
    flash_kernel<<<dim3(Tdim / 64, Hdim, Bdim), 256, flash_smem>>>(q, k, v, temp, ao);

    sgemm_kernel<0><<<gg, 256>>>(ao, Wo, bo, out, Mrows, Cdim, Cdim);
}

// round 2
// speedup vs baseline: 1.1071x; 1.1071x over previous
#include <cuda_runtime.h>
#include <math.h>

#define Bdim 2
#define Tdim 2048
#define Cdim 1024
#define Hdim 16
#define Sdim 16
#define HDdim 64
#define Mrows (Bdim*Tdim)   /* 4096 */
#define NCH 8               /* scan chunks */
#define CHT (Tdim/NCH)      /* 256 t per chunk */

// ---------------- device scratch (static, no allocation) ----------------
__device__ float g_xbase[Mrows*Cdim];
__device__ float g_delta[Mrows*Cdim];
__device__ float g_Bmat [Mrows*Sdim];
__device__ float g_Cmat [Mrows*Sdim];
__device__ float g_y    [Mrows*Cdim];
__device__ float g_cumD [Mrows*Cdim];
__device__ float g_hend [Bdim*NCH*Cdim*Sdim];
__device__ float g_hin  [Bdim*NCH*Cdim*Sdim];
__device__ float g_hyb  [Mrows*Cdim];
__device__ float g_q    [Mrows*Cdim];
__device__ float g_k    [Mrows*Cdim];
__device__ float g_v    [Mrows*Cdim];
__device__ float g_ao   [Mrows*Cdim];

// ---------------- SGEMM: out = act(A @ W + bias) ----------------
template<int MODE>
__global__ __launch_bounds__(256, 2)
void sgemm_kernel(const float* __restrict__ A, const float* __restrict__ W,
                  const float* __restrict__ bias, float* __restrict__ out,
                  int M, int N, int K)
{
    __shared__ float As[8][128];
    __shared__ float Bs[8][128];
    const int tid  = threadIdx.x;
    const int row0 = blockIdx.y * 128;
    const int col0 = blockIdx.x * 128;
    const int arow = tid >> 1;
    const int ak   = (tid & 1) << 2;
    const int brow = tid >> 5;
    const int bcol = (tid & 31) << 2;
    const int tr   = (tid >> 4) << 2;
    const int tc   = (tid & 15) << 2;

    float acc[8][8];
#pragma unroll
    for (int i = 0; i < 8; i++)
#pragma unroll
        for (int j = 0; j < 8; j++) acc[i][j] = 0.f;

    const float* Ap = A + (size_t)(row0 + arow) * K + ak;
    const float* Wp = W + (size_t)brow * N + col0 + bcol;

    for (int k0 = 0; k0 < K; k0 += 8) {
        float4 a4 = *(const float4*)(Ap + k0);
        float4 b4 = *(const float4*)(Wp + (size_t)k0 * N);
        As[ak + 0][arow] = a4.x;
        As[ak + 1][arow] = a4.y;
        As[ak + 2][arow] = a4.z;
        As[ak + 3][arow] = a4.w;
        *(float4*)&Bs[brow][bcol] = b4;
        __syncthreads();
#pragma unroll
        for (int k = 0; k < 8; k++) {
            float4 a0 = *(const float4*)&As[k][tr];
            float4 a1 = *(const float4*)&As[k][tr + 64];
            float4 b0 = *(const float4*)&Bs[k][tc];
            float4 b1 = *(const float4*)&Bs[k][tc + 64];
            float ar[8] = {a0.x,a0.y,a0.z,a0.w,a1.x,a1.y,a1.z,a1.w};
            float br[8] = {b0.x,b0.y,b0.z,b0.w,b1.x,b1.y,b1.z,b1.w};
#pragma unroll
            for (int i = 0; i < 8; i++)
#pragma unroll
                for (int j = 0; j < 8; j++)
                    acc[i][j] = fmaf(ar[i], br[j], acc[i][j]);
        }
        __syncthreads();
    }

#pragma unroll
    for (int ih = 0; ih < 2; ih++) {
#pragma unroll
        for (int i = 0; i < 4; i++) {
            int r = row0 + ih * 64 + tr + i;
#pragma unroll
            for (int jh = 0; jh < 2; jh++) {
                int cb = col0 + jh * 64 + tc;
                float4 bv = *(const float4*)(bias + cb);
                float4 vv;
                vv.x = acc[ih*4+i][jh*4+0] + bv.x;
                vv.y = acc[ih*4+i][jh*4+1] + bv.y;
                vv.z = acc[ih*4+i][jh*4+2] + bv.z;
                vv.w = acc[ih*4+i][jh*4+3] + bv.w;
                if (MODE == 1) {
                    vv.x = (vv.x > 20.f) ? vv.x : log1pf(expf(vv.x));
                    vv.y = (vv.y > 20.f) ? vv.y : log1pf(expf(vv.y));
                    vv.z = (vv.z > 20.f) ? vv.z : log1pf(expf(vv.z));
                    vv.w = (vv.w > 20.f) ? vv.w : log1pf(expf(vv.w));
                }
                if (MODE == 2) {
                    int b = r >> 11, t = r & (Tdim - 1);
                    int h = cb >> 6, d = cb & 63;
                    float* dst = out + (((size_t)(b * Hdim + h) * Tdim + t) << 6) + d;
                    *(float4*)dst = vv;
                } else {
                    *(float4*)(out + (size_t)r * N + cb) = vv;
                }
            }
        }
    }
}

// ---------------- skinny GEMM: Bm = x@WB, Cm = x@WC (N=16) ----------------
__global__ __launch_bounds__(256)
void skinny_kernel(const float* __restrict__ x, const float* __restrict__ WB,
                   const float* __restrict__ WC,
                   float* __restrict__ Bm, float* __restrict__ Cm)
{
    __shared__ float wb[128 * 16];
    __shared__ float wc[128 * 16];
    __shared__ float xs[16][128];
    const int tid = threadIdx.x;
    const int m0  = blockIdx.x * 16;
    const int rl  = tid >> 4;
    const int s   = tid & 15;
    float accB = 0.f, accC = 0.f;

    for (int k0 = 0; k0 < Cdim; k0 += 128) {
#pragma unroll
        for (int u = 0; u < 2; u++) {
            int idx = tid * 8 + u * 4;
            *(float4*)&wb[idx] = *(const float4*)(WB + k0 * 16 + idx);
            *(float4*)&wc[idx] = *(const float4*)(WC + k0 * 16 + idx);
        }
        {
            int row = tid >> 4;
            int cc  = (tid & 15) * 8;
            const float* xp = x + (size_t)(m0 + row) * Cdim + k0 + cc;
            *(float4*)&xs[row][cc]     = *(const float4*)(xp);
            *(float4*)&xs[row][cc + 4] = *(const float4*)(xp + 4);
        }
        __syncthreads();
#pragma unroll 8
        for (int kk = 0; kk < 128; kk++) {
            float xv = xs[rl][kk];
            accB = fmaf(xv, wb[kk * 16 + s], accB);
            accC = fmaf(xv, wc[kk * 16 + s], accC);
        }
        __syncthreads();
    }
    Bm[(size_t)(m0 + rl) * 16 + s] = accB;
    Cm[(size_t)(m0 + rl) * 16 + s] = accC;
}

// ================= chunked SSM scan =================
// Pass A: per-chunk local scan (h_in = 0). Emits y_local, cumD, h_end.
// Block: 256 threads = (c-local 16) x (s 16); one (b, chunk, c-tile).
#define TTA 32
__global__ __launch_bounds__(256)
void scanA_kernel(const float* __restrict__ A_log,
                  const float* __restrict__ delta,
                  const float* __restrict__ xb,
                  const float* __restrict__ Bm,
                  const float* __restrict__ Cm,
                  float* __restrict__ ylocal,
                  float* __restrict__ cumD,
                  float* __restrict__ hend)
{
    __shared__ float2 sdx[TTA][16];   // {delta, xbase} per [t][c]
    __shared__ float2 sbc[TTA][16];   // {B, C} per [t][s]

    const int tid = threadIdx.x;
    const int s   = tid & 15;
    const int cl  = tid >> 4;
    const int c0  = blockIdx.x * 16;
    const int ch  = blockIdx.y;
    const int b   = blockIdx.z;
    const int c   = c0 + cl;
    const int t00 = ch * CHT;
    const float LOG2E = 1.4426950408889634f;
    const float a2 = -expf(A_log[c * Sdim + s]) * LOG2E;

    float h = 0.f, cum = 0.f;

    for (int t0 = t00; t0 < t00 + CHT; t0 += TTA) {
        __syncthreads();
        // stage delta/xb: TTA*16 = 512 float2; 2 per thread
#pragma unroll
        for (int u = 0; u < 2; u++) {
            int e = tid + u * 256;
            int tt = e >> 4, cc = e & 15;
            size_t g = ((size_t)b * Tdim + t0 + tt) * Cdim + c0 + cc;
            sdx[tt][cc] = make_float2(delta[g], xb[g]);
        }
        // stage B/C: same shape
#pragma unroll
        for (int u = 0; u < 2; u++) {
            int e = tid + u * 256;
            int tt = e >> 4, ss = e & 15;
            size_t g = ((size_t)b * Tdim + t0 + tt) * Sdim + ss;
            sbc[tt][ss] = make_float2(Bm[g], Cm[g]);
        }
        __syncthreads();

#pragma unroll
        for (int tt = 0; tt < TTA; tt++) {
            float2 dx = sdx[tt][cl];
            float2 bc = sbc[tt][s];
            cum += dx.x;
            float e = exp2f(dx.x * a2);
            h = fmaf(e, h, dx.x * dx.y * bc.x);
            float p = h * bc.y;
            p += __shfl_xor_sync(0xffffffffu, p, 8);
            p += __shfl_xor_sync(0xffffffffu, p, 4);
            p += __shfl_xor_sync(0xffffffffu, p, 2);
            p += __shfl_xor_sync(0xffffffffu, p, 1);
            if (s == 0) {
                size_t g = ((size_t)b * Tdim + t0 + tt) * Cdim + c;
                ylocal[g] = p;
                cumD[g]   = cum;
            }
        }
    }
    hend[(((size_t)b * NCH + ch) * Cdim + c) * Sdim + s] = h;
}

// Pass B: carry h across chunks (sequential over NCH=8, tiny).
__global__ __launch_bounds__(256)
void scanB_kernel(const float* __restrict__ A_log,
                  const float* __restrict__ cumD,
                  const float* __restrict__ hend,
                  float* __restrict__ hin)
{
    const int gid = blockIdx.x * 256 + threadIdx.x;
    const int s = gid & 15;
    const int c = (gid >> 4) & (Cdim - 1);
    const int b = gid >> 14;
    const float LOG2E = 1.4426950408889634f;
    const float a2 = -expf(A_log[c * Sdim + s]) * LOG2E;

    float h = 0.f;
#pragma unroll
    for (int k = 0; k < NCH; k++) {
        size_t idx = (((size_t)b * NCH + k) * Cdim + c) * Sdim + s;
        hin[idx] = h;
        float sd = cumD[((size_t)b * Tdim + k * CHT + CHT - 1) * Cdim + c];
        h = fmaf(exp2f(a2 * sd), h, hend[idx]);
    }
}

// Pass C: y = y_local + sum_s C_t[s] * exp2(a2[s]*cumD_t) * h_in[s]
// Block: 256 threads = (t-local 16) x (c-local 16); one (b, t-tile, c-tile).
__global__ __launch_bounds__(256)
void scanC_kernel(const float* __restrict__ A_log,
                  const float* __restrict__ Cm,
                  const float* __restrict__ hin,
                  const float* __restrict__ cumD,
                  float* __restrict__ y)
{
    __shared__ float a2s[16][17];   // [c-local][s]
    __shared__ float hns[16][17];   // [c-local][s]
    __shared__ float cts[16][16];   // [t-local][s]

    const int tid = threadIdx.x;
    const int c0  = blockIdx.x * 16;
    const int t0  = blockIdx.y * 16;
    const int b   = blockIdx.z;
    const int ch  = t0 / CHT;
    const float LOG2E = 1.4426950408889634f;

    {   // one element each
        int i = tid >> 4, j = tid & 15;
        a2s[i][j] = -expf(A_log[(c0 + i) * Sdim + j]) * LOG2E;
        hns[i][j] = hin[(((size_t)b * NCH + ch) * Cdim + c0 + i) * Sdim + j];
        cts[i][j] = Cm[((size_t)b * Tdim + t0 + i) * Sdim + j];
    }
    __syncthreads();

    const int tl = tid >> 4;
    const int cl = tid & 15;
    size_t g = ((size_t)b * Tdim + t0 + tl) * Cdim + c0 + cl;
    float cd  = cumD[g];
    float acc = y[g];
#pragma unroll
    for (int s = 0; s < 16; s++)
        acc = fmaf(cts[tl][s] * hns[cl][s], exp2f(a2s[cl][s] * cd), acc);
    y[g] = acc;
}

// ---------------- add + LayerNorm ----------------
__global__ __launch_bounds__(256)
void addln_kernel(const float* __restrict__ xb, const float* __restrict__ y,
                  const float* __restrict__ gam, const float* __restrict__ bet,
                  float* __restrict__ out)
{
    __shared__ float red[16];
    const int row = blockIdx.x, tid = threadIdx.x;
    const float* p1 = xb + (size_t)row * Cdim;
    const float* p2 = y  + (size_t)row * Cdim;
    float v[4]; float s = 0.f, s2 = 0.f;
#pragma unroll
    for (int i = 0; i < 4; i++) {
        int idx = tid + i * 256;
        v[i] = p1[idx] + p2[idx];
        s += v[i]; s2 += v[i] * v[i];
    }
#pragma unroll
    for (int o = 16; o; o >>= 1) {
        s  += __shfl_xor_sync(0xffffffffu, s,  o);
        s2 += __shfl_xor_sync(0xffffffffu, s2, o);
    }
    if ((tid & 31) == 0) { red[tid >> 5] = s; red[(tid >> 5) + 8] = s2; }
    __syncthreads();
    float S = 0.f, S2 = 0.f;
#pragma unroll
    for (int w = 0; w < 8; w++) { S += red[w]; S2 += red[w + 8]; }
    float mean = S * (1.f / Cdim);
    float var  = S2 * (1.f / Cdim) - mean * mean;
    float rs   = rsqrtf(var + 1e-5f);
#pragma unroll
    for (int i = 0; i < 4; i++) {
        int idx = tid + i * 256;
        out[(size_t)row * Cdim + idx] = (v[i] - mean) * rs * gam[idx] + bet[idx];
    }
}

// ---------------- causal flash attention, fp32, 64x64 tiles --------------
#define FPAD 68
__global__ __launch_bounds__(256)
void flash_kernel(const float* __restrict__ q, const float* __restrict__ k,
                  const float* __restrict__ v, const float* __restrict__ temp,
                  float* __restrict__ out)
{
    extern __shared__ float sm[];
    float* Qt   = sm;
    float* Kt   = Qt + 64 * FPAD;
    float* Vs   = Kt + 64 * FPAD;
    float* St   = Vs + 64 * FPAD;
    float* mrow = St + 64 * FPAD;
    float* lrow = mrow + 64;
    float* arow = lrow + 64;

    const int tid = threadIdx.x;
    const int qt = blockIdx.x, h = blockIdx.y, b = blockIdx.z;
    const int bh = b * Hdim + h;
    const float* qb = q + ((size_t)bh * Tdim + qt * 64) * HDdim;
    const float* kb = k + (size_t)bh * Tdim * HDdim;
    const float* vb = v + (size_t)bh * Tdim * HDdim;

    float tv = temp[h];
    float sp = (tv > 20.f) ? tv : log1pf(expf(tv));
    float sc = sp * (1.4426950408889634f / 8.0f);

    {
        int r  = tid >> 2;
        int d4 = (tid & 3) * 16;
#pragma unroll
        for (int u = 0; u < 4; u++) {
            float4 qv = *(const float4*)(qb + r * 64 + d4 + u * 4);
            Qt[(d4 + u*4 + 0) * FPAD + r] = qv.x * sc;
            Qt[(d4 + u*4 + 1) * FPAD + r] = qv.y * sc;
            Qt[(d4 + u*4 + 2) * FPAD + r] = qv.z * sc;
            Qt[(d4 + u*4 + 3) * FPAD + r] = qv.w * sc;
        }
    }
    if (tid < 64) { mrow[tid] = -1e30f; lrow[tid] = 0.f; }

    const int tr = (tid >> 4) * 4;
    const int tc = (tid & 15) * 4;
    float o[4][4] = {};

    for (int j = 0; j <= qt; j++) {
        __syncthreads();
        {
            int r  = tid >> 2;
            int d4 = (tid & 3) * 16;
            const float* kr = kb + ((size_t)j * 64 + r) * 64 + d4;
            const float* vr = vb + ((size_t)j * 64 + r) * 64 + d4;
#pragma unroll
            for (int u = 0; u < 4; u++) {
                float4 k4 = *(const float4*)(kr + u * 4);
                Kt[(d4 + u*4 + 0) * FPAD + r] = k4.x;
                Kt[(d4 + u*4 + 1) * FPAD + r] = k4.y;
                Kt[(d4 + u*4 + 2) * FPAD + r] = k4.z;
                Kt[(d4 + u*4 + 3) * FPAD + r] = k4.w;
                *(float4*)&Vs[r * FPAD + d4 + u * 4] = *(const float4*)(vr + u * 4);
            }
        }
        __syncthreads();

        float sacc[4][4] = {};
#pragma unroll 8
        for (int kk = 0; kk < 64; kk++) {
            float4 qv = *(const float4*)&Qt[kk * FPAD + tr];
            float4 kv4 = *(const float4*)&Kt[kk * FPAD + tc];
            float qa[4] = {qv.x, qv.y, qv.z, qv.w};
            float ka[4] = {kv4.x, kv4.y, kv4.z, kv4.w};
#pragma unroll
            for (int i = 0; i < 4; i++)
#pragma unroll
                for (int jj = 0; jj < 4; jj++)
                    sacc[i][jj] = fmaf(qa[i], ka[jj], sacc[i][jj]);
        }
        const bool diag = (j == qt);
#pragma unroll
        for (int i = 0; i < 4; i++)
#pragma unroll
            for (int jj = 0; jj < 4; jj++) {
                float val = sacc[i][jj];
                if (diag && (tc + jj > tr + i)) val = -1e30f;
                St[(tc + jj) * FPAD + (tr + i)] = val;
            }
        __syncthreads();

        {
            int row = tid >> 2, seg = tid & 3;
            float mx = -1e30f;
#pragma unroll
            for (int i = 0; i < 16; i++)
                mx = fmaxf(mx, St[(seg * 16 + i) * FPAD + row]);
            mx = fmaxf(mx, __shfl_xor_sync(0xffffffffu, mx, 1));
            mx = fmaxf(mx, __shfl_xor_sync(0xffffffffu, mx, 2));
            float mold = mrow[row];
            float mnew = fmaxf(mold, mx);
            float al   = exp2f(mold - mnew);
            float ssum = 0.f;
#pragma unroll
            for (int i = 0; i < 16; i++) {
                float p = exp2f(St[(seg * 16 + i) * FPAD + row] - mnew);
                St[(seg * 16 + i) * FPAD + row] = p;
                ssum += p;
            }
            ssum += __shfl_xor_sync(0xffffffffu, ssum, 1);
            ssum += __shfl_xor_sync(0xffffffffu, ssum, 2);
            if (seg == 0) {
                mrow[row] = mnew;
                arow[row] = al;
                lrow[row] = lrow[row] * al + ssum;
            }
        }
        __syncthreads();

#pragma unroll
        for (int i = 0; i < 4; i++) {
            float al = arow[tr + i];
#pragma unroll
            for (int jj = 0; jj < 4; jj++) o[i][jj] *= al;
        }
#pragma unroll 8
        for (int kk = 0; kk < 64; kk++) {
            float4 pv = *(const float4*)&St[kk * FPAD + tr];
            float4 vv4 = *(const float4*)&Vs[kk * FPAD + tc];
            float pa[4] = {pv.x, pv.y, pv.z, pv.w};
            float va[4] = {vv4.x, vv4.y, vv4.z, vv4.w};
#pragma unroll
            for (int i = 0; i < 4; i++)
#pragma unroll
                for (int jj = 0; jj < 4; jj++)
                    o[i][jj] = fmaf(pa[i], va[jj], o[i][jj]);
        }
    }

#pragma unroll
    for (int i = 0; i < 4; i++) {
        int r = tr + i;
        float linv = 1.0f / lrow[r];
        float4 vo;
        vo.x = o[i][0] * linv; vo.y = o[i][1] * linv;
        vo.z = o[i][2] * linv; vo.w = o[i][3] * linv;
        size_t dst = ((size_t)b * Tdim + (size_t)qt * 64 + r) * Cdim + h * HDdim + tc;
        *(float4*)(out + dst) = vo;
    }
}

// ---------------- host ----------------
static float* symaddr(const void* s) {
    void* p = nullptr;
    cudaGetSymbolAddress(&p, s);
    return (float*)p;
}

extern "C" void kernel_launch(void* const* d_in, const int* in_sizes, int n_in,
                              void* d_out, int out_size)
{
    const float* x     = (const float*)d_in[0];
    const float* A_log = (const float*)d_in[1];
    const float* Wd    = (const float*)d_in[2];
    const float* bd    = (const float*)d_in[3];
    const float* WB    = (const float*)d_in[4];
    const float* WC    = (const float*)d_in[5];
    const float* Wq    = (const float*)d_in[6];
    const float* bq    = (const float*)d_in[7];
    const float* Wk    = (const float*)d_in[8];
    const float* bk    = (const float*)d_in[9];
    const float* Wv    = (const float*)d_in[10];
    const float* bv    = (const float*)d_in[11];
    const float* Wx    = (const float*)d_in[12];
    const float* bx    = (const float*)d_in[13];
    const float* Wo    = (const float*)d_in[14];
    const float* bo    = (const float*)d_in[15];
    const float* lng   = (const float*)d_in[16];
    const float* lnb   = (const float*)d_in[17];
    const float* temp  = (const float*)d_in[18];
    float* out = (float*)d_out;

    float* xbase = symaddr(g_xbase);
    float* delta = symaddr(g_delta);
    float* Bm    = symaddr(g_Bmat);
    float* Cm    = symaddr(g_Cmat);
    float* y     = symaddr(g_y);
    float* cumD  = symaddr(g_cumD);
    float* hend  = symaddr(g_hend);
    float* hin   = symaddr(g_hin);
    float* hyb   = symaddr(g_hyb);
    float* q     = symaddr(g_q);
    float* k     = symaddr(g_k);
    float* v     = symaddr(g_v);
    float* ao    = symaddr(g_ao);

    dim3 gg(Cdim / 128, Mrows / 128);   // (8, 32)

    sgemm_kernel<0><<<gg, 256>>>(x, Wx, bx, xbase, Mrows, Cdim, Cdim);
    sgemm_kernel<1><<<gg, 256>>>(x, Wd, bd, delta, Mrows, Cdim, Cdim);
    skinny_kernel<<<Mrows / 16, 256>>>(x, WB, WC, Bm, Cm);

    scanA_kernel<<<dim3(Cdim / 16, NCH, Bdim), 256>>>(A_log, delta, xbase, Bm, Cm, y, cumD, hend);
    scanB_kernel<<<(Bdim * Cdim * Sdim) / 256, 256>>>(A_log, cumD, hend, hin);
    scanC_kernel<<<dim3(Cdim / 16, Tdim / 16, Bdim), 256>>>(A_log, Cm, hin, cumD, y);

    addln_kernel<<<Mrows, 256>>>(xbase, y, lng, lnb, hyb);
    sgemm_kernel<2><<<gg, 256>>>(hyb, Wq, bq, q, Mrows, Cdim, Cdim);
    sgemm_kernel<2><<<gg, 256>>>(hyb, Wk, bk, k, Mrows, Cdim, Cdim);
    sgemm_kernel<2><<<gg, 256>>>(hyb, Wv, bv, v, Mrows, Cdim, Cdim);

    const int flash_smem = (4 * 64 * FPAD + 3 * 64) * (int)sizeof(float);
    cudaFuncSetAttribute(flash_kernel, cudaFuncAttributeMaxDynamicSharedMemorySize, flash_smem);
    flash_kernel<<<dim3(Tdim / 64, Hdim, Bdim), 256, flash_smem>>>(q, k, v, temp, ao);

    sgemm_kernel<0><<<gg, 256>>>(ao, Wo, bo, out, Mrows, Cdim, Cdim);
}

// round 3
// speedup vs baseline: 1.2053x; 1.0887x over previous
#include <cuda_runtime.h>
#include <math.h>
#include <stdint.h>

#define Bdim 2
#define Tdim 2048
#define Cdim 1024
#define Hdim 16
#define Sdim 16
#define HDdim 64
#define Mrows (Bdim*Tdim)   /* 4096 */
#define NCH 16              /* scan chunks */
#define CHT (Tdim/NCH)      /* 128 t per chunk */

// ---------------- device scratch (static, no allocation) ----------------
__device__ float g_xbase[Mrows*Cdim];
__device__ float g_delta[Mrows*Cdim];
__device__ float g_Bmat [Mrows*Sdim];
__device__ float g_Cmat [Mrows*Sdim];
__device__ float g_y    [Mrows*Cdim];
__device__ float g_cumD [Mrows*Cdim];
__device__ float g_hend [Bdim*NCH*Cdim*Sdim];
__device__ float g_hin  [Bdim*NCH*Cdim*Sdim];
__device__ float g_hyb  [Mrows*Cdim];
__device__ float g_q    [Mrows*Cdim];
__device__ float g_k    [Mrows*Cdim];
__device__ float g_v    [Mrows*Cdim];
__device__ float g_ao   [Mrows*Cdim];

// ---------------- tf32 helpers ----------------
__device__ __forceinline__ uint32_t f2tf32(float x) {
    uint32_t r;
    asm("cvt.rna.tf32.f32 %0, %1;" : "=r"(r) : "f"(x));
    return r;
}
__device__ __forceinline__ void split_tf32(float x, uint32_t& hi, uint32_t& lo) {
    hi = f2tf32(x);
    lo = f2tf32(x - __uint_as_float(hi));
}
__device__ __forceinline__ void mma_tf32(float* d, const uint32_t* a, const uint32_t* b) {
    asm volatile(
        "mma.sync.aligned.m16n8k8.row.col.f32.tf32.tf32.f32 "
        "{%0,%1,%2,%3}, {%4,%5,%6,%7}, {%8,%9}, {%0,%1,%2,%3};"
        : "+f"(d[0]), "+f"(d[1]), "+f"(d[2]), "+f"(d[3])
        : "r"(a[0]), "r"(a[1]), "r"(a[2]), "r"(a[3]), "r"(b[0]), "r"(b[1]));
}

// ---------------- tensor-core GEMM (3xTF32): out = act(A @ W + bias) ------
// A: MxK row-major, W: KxN row-major. MODE 0 plain, 1 softplus, 2 head-scatter.
// BM=BN=128, BK=16, 256 threads = 8 warps (2m x 4n), warp tile 64x32.
#define APAD 136
template<int MODE>
__global__ __launch_bounds__(256)
void tgemm_kernel(const float* __restrict__ A, const float* __restrict__ W,
                  const float* __restrict__ bias, float* __restrict__ out,
                  int M, int N, int K)
{
    __shared__ float As[16][APAD];
    __shared__ float Bs[16][APAD];

    const int tid  = threadIdx.x;
    const int lane = tid & 31;
    const int warp = tid >> 5;
    const int wm   = (warp >> 2) * 64;
    const int wn   = (warp & 3) * 32;
    const int gr   = lane >> 2;
    const int ctid = lane & 3;
    const int row0 = blockIdx.y * 128;
    const int col0 = blockIdx.x * 128;

    float acc[4][4][4];
#pragma unroll
    for (int i = 0; i < 4; i++)
#pragma unroll
        for (int j = 0; j < 4; j++)
#pragma unroll
            for (int e = 0; e < 4; e++) acc[i][j][e] = 0.f;

    // global load indices
    const int am  = tid & 127;          // A: m within tile
    const int aq  = tid >> 7;           // A: k-quad base (0 or 1), +2 for u=1
    const int bn4 = tid & 31;           // B: n-quad
    const int bk  = tid >> 5;           // B: k row (0..7), +8 for u=1

    float4 av[2], bv[2];
    // prefetch tile 0
    {
        const float* Ap = A + (size_t)(row0 + am) * K + 4 * aq;
        av[0] = *(const float4*)(Ap);
        av[1] = *(const float4*)(Ap + 8);
        const float* Wp = W + (size_t)bk * N + col0 + 4 * bn4;
        bv[0] = *(const float4*)(Wp);
        bv[1] = *(const float4*)(Wp + (size_t)8 * N);
    }

    for (int k0 = 0; k0 < K; k0 += 16) {
        __syncthreads();
        // store staged tile
        As[4*aq + 0][am] = av[0].x;
        As[4*aq + 1][am] = av[0].y;
        As[4*aq + 2][am] = av[0].z;
        As[4*aq + 3][am] = av[0].w;
        As[4*aq + 8][am] = av[1].x;
        As[4*aq + 9][am] = av[1].y;
        As[4*aq +10][am] = av[1].z;
        As[4*aq +11][am] = av[1].w;
        *(float4*)&Bs[bk    ][4*bn4] = bv[0];
        *(float4*)&Bs[bk + 8][4*bn4] = bv[1];
        __syncthreads();

        // prefetch next tile
        if (k0 + 16 < K) {
            const float* Ap = A + (size_t)(row0 + am) * K + k0 + 16 + 4 * aq;
            av[0] = *(const float4*)(Ap);
            av[1] = *(const float4*)(Ap + 8);
            const float* Wp = W + (size_t)(k0 + 16 + bk) * N + col0 + 4 * bn4;
            bv[0] = *(const float4*)(Wp);
            bv[1] = *(const float4*)(Wp + (size_t)8 * N);
        }

#pragma unroll
        for (int ks = 0; ks < 16; ks += 8) {
            uint32_t ahi[4][4], alo[4][4];
#pragma unroll
            for (int mt = 0; mt < 4; mt++) {
                int m = wm + mt * 16 + gr;
                split_tf32(As[ks + ctid    ][m    ], ahi[mt][0], alo[mt][0]);
                split_tf32(As[ks + ctid    ][m + 8], ahi[mt][1], alo[mt][1]);
                split_tf32(As[ks + ctid + 4][m    ], ahi[mt][2], alo[mt][2]);
                split_tf32(As[ks + ctid + 4][m + 8], ahi[mt][3], alo[mt][3]);
            }
            uint32_t bhi[4][2], blo[4][2];
#pragma unroll
            for (int nt = 0; nt < 4; nt++) {
                int n = wn + nt * 8 + gr;
                split_tf32(Bs[ks + ctid    ][n], bhi[nt][0], blo[nt][0]);
                split_tf32(Bs[ks + ctid + 4][n], bhi[nt][1], blo[nt][1]);
            }
#pragma unroll
            for (int mt = 0; mt < 4; mt++)
#pragma unroll
                for (int nt = 0; nt < 4; nt++) {
                    mma_tf32(acc[mt][nt], ahi[mt], bhi[nt]);
                    mma_tf32(acc[mt][nt], alo[mt], bhi[nt]);
                    mma_tf32(acc[mt][nt], ahi[mt], blo[nt]);
                }
        }
    }

    // epilogue
#pragma unroll
    for (int mt = 0; mt < 4; mt++) {
#pragma unroll
        for (int nt = 0; nt < 4; nt++) {
            int c = col0 + wn + nt * 8 + 2 * ctid;
            float2 bb = *(const float2*)(bias + c);
#pragma unroll
            for (int half = 0; half < 2; half++) {
                int r = row0 + wm + mt * 16 + gr + half * 8;
                float vx = acc[mt][nt][half * 2 + 0] + bb.x;
                float vy = acc[mt][nt][half * 2 + 1] + bb.y;
                if (MODE == 1) {
                    vx = (vx > 20.f) ? vx : log1pf(expf(vx));
                    vy = (vy > 20.f) ? vy : log1pf(expf(vy));
                }
                float2 vv = make_float2(vx, vy);
                if (MODE == 2) {
                    int b = r >> 11, t = r & (Tdim - 1);
                    int h = c >> 6, d = c & 63;
                    float* dst = out + (((size_t)(b * Hdim + h) * Tdim + t) << 6) + d;
                    *(float2*)dst = vv;
                } else {
                    *(float2*)(out + (size_t)r * N + c) = vv;
                }
            }
        }
    }
}

// ---------------- skinny GEMM: Bm = x@WB, Cm = x@WC (N=16) ----------------
__global__ __launch_bounds__(256)
void skinny_kernel(const float* __restrict__ x, const float* __restrict__ WB,
                   const float* __restrict__ WC,
                   float* __restrict__ Bm, float* __restrict__ Cm)
{
    __shared__ float wb[128 * 16];
    __shared__ float wc[128 * 16];
    __shared__ float xs[16][128];
    const int tid = threadIdx.x;
    const int m0  = blockIdx.x * 16;
    const int rl  = tid >> 4;
    const int s   = tid & 15;
    float accB = 0.f, accC = 0.f;

    for (int k0 = 0; k0 < Cdim; k0 += 128) {
#pragma unroll
        for (int u = 0; u < 2; u++) {
            int idx = tid * 8 + u * 4;
            *(float4*)&wb[idx] = *(const float4*)(WB + k0 * 16 + idx);
            *(float4*)&wc[idx] = *(const float4*)(WC + k0 * 16 + idx);
        }
        {
            int row = tid >> 4;
            int cc  = (tid & 15) * 8;
            const float* xp = x + (size_t)(m0 + row) * Cdim + k0 + cc;
            *(float4*)&xs[row][cc]     = *(const float4*)(xp);
            *(float4*)&xs[row][cc + 4] = *(const float4*)(xp + 4);
        }
        __syncthreads();
#pragma unroll 8
        for (int kk = 0; kk < 128; kk++) {
            float xv = xs[rl][kk];
            accB = fmaf(xv, wb[kk * 16 + s], accB);
            accC = fmaf(xv, wc[kk * 16 + s], accC);
        }
        __syncthreads();
    }
    Bm[(size_t)(m0 + rl) * 16 + s] = accB;
    Cm[(size_t)(m0 + rl) * 16 + s] = accC;
}

// ================= chunked SSM scan =================
#define TTA 32
__global__ __launch_bounds__(256)
void scanA_kernel(const float* __restrict__ A_log,
                  const float* __restrict__ delta,
                  const float* __restrict__ xb,
                  const float* __restrict__ Bm,
                  const float* __restrict__ Cm,
                  float* __restrict__ ylocal,
                  float* __restrict__ cumD,
                  float* __restrict__ hend)
{
    __shared__ float2 sdx[TTA][16];
    __shared__ float2 sbc[TTA][16];

    const int tid = threadIdx.x;
    const int s   = tid & 15;
    const int cl  = tid >> 4;
    const int c0  = blockIdx.x * 16;
    const int ch  = blockIdx.y;
    const int b   = blockIdx.z;
    const int c   = c0 + cl;
    const int t00 = ch * CHT;
    const float LOG2E = 1.4426950408889634f;
    const float a2 = -expf(A_log[c * Sdim + s]) * LOG2E;

    float h = 0.f, cum = 0.f;

    for (int t0 = t00; t0 < t00 + CHT; t0 += TTA) {
        __syncthreads();
#pragma unroll
        for (int u = 0; u < 2; u++) {
            int e = tid + u * 256;
            int tt = e >> 4, cc = e & 15;
            size_t g = ((size_t)b * Tdim + t0 + tt) * Cdim + c0 + cc;
            sdx[tt][cc] = make_float2(delta[g], xb[g]);
        }
#pragma unroll
        for (int u = 0; u < 2; u++) {
            int e = tid + u * 256;
            int tt = e >> 4, ss = e & 15;
            size_t g = ((size_t)b * Tdim + t0 + tt) * Sdim + ss;
            sbc[tt][ss] = make_float2(Bm[g], Cm[g]);
        }
        __syncthreads();

#pragma unroll
        for (int tt = 0; tt < TTA; tt++) {
            float2 dx = sdx[tt][cl];
            float2 bc = sbc[tt][s];
            cum += dx.x;
            float e = exp2f(dx.x * a2);
            h = fmaf(e, h, dx.x * dx.y * bc.x);
            float p = h * bc.y;
            p += __shfl_xor_sync(0xffffffffu, p, 8);
            p += __shfl_xor_sync(0xffffffffu, p, 4);
            p += __shfl_xor_sync(0xffffffffu, p, 2);
            p += __shfl_xor_sync(0xffffffffu, p, 1);
            if (s == 0) {
                size_t g = ((size_t)b * Tdim + t0 + tt) * Cdim + c;
                ylocal[g] = p;
                cumD[g]   = cum;
            }
        }
    }
    hend[(((size_t)b * NCH + ch) * Cdim + c) * Sdim + s] = h;
}

__global__ __launch_bounds__(256)
void scanB_kernel(const float* __restrict__ A_log,
                  const float* __restrict__ cumD,
                  const float* __restrict__ hend,
                  float* __restrict__ hin)
{
    const int gid = blockIdx.x * 256 + threadIdx.x;
    const int s = gid & 15;
    const int c = (gid >> 4) & (Cdim - 1);
    const int b = gid >> 14;
    const float LOG2E = 1.4426950408889634f;
    const float a2 = -expf(A_log[c * Sdim + s]) * LOG2E;

    float h = 0.f;
#pragma unroll
    for (int k = 0; k < NCH; k++) {
        size_t idx = (((size_t)b * NCH + k) * Cdim + c) * Sdim + s;
        hin[idx] = h;
        float sd = cumD[((size_t)b * Tdim + k * CHT + CHT - 1) * Cdim + c];
        h = fmaf(exp2f(a2 * sd), h, hend[idx]);
    }
}

__global__ __launch_bounds__(256)
void scanC_kernel(const float* __restrict__ A_log,
                  const float* __restrict__ Cm,
                  const float* __restrict__ hin,
                  const float* __restrict__ cumD,
                  float* __restrict__ y)
{
    __shared__ float a2s[16][17];
    __shared__ float hns[16][17];
    __shared__ float cts[16][16];

    const int tid = threadIdx.x;
    const int c0  = blockIdx.x * 16;
    const int t0  = blockIdx.y * 16;
    const int b   = blockIdx.z;
    const int ch  = t0 / CHT;
    const float LOG2E = 1.4426950408889634f;

    {
        int i = tid >> 4, j = tid & 15;
        a2s[i][j] = -expf(A_log[(c0 + i) * Sdim + j]) * LOG2E;
        hns[i][j] = hin[(((size_t)b * NCH + ch) * Cdim + c0 + i) * Sdim + j];
        cts[i][j] = Cm[((size_t)b * Tdim + t0 + i) * Sdim + j];
    }
    __syncthreads();

    const int tl = tid >> 4;
    const int cl = tid & 15;
    size_t g = ((size_t)b * Tdim + t0 + tl) * Cdim + c0 + cl;
    float cd  = cumD[g];
    float acc = y[g];
#pragma unroll
    for (int s = 0; s < 16; s++)
        acc = fmaf(cts[tl][s] * hns[cl][s], exp2f(a2s[cl][s] * cd), acc);
    y[g] = acc;
}

// ---------------- add + LayerNorm ----------------
__global__ __launch_bounds__(256)
void addln_kernel(const float* __restrict__ xb, const float* __restrict__ y,
                  const float* __restrict__ gam, const float* __restrict__ bet,
                  float* __restrict__ out)
{
    __shared__ float red[16];
    const int row = blockIdx.x, tid = threadIdx.x;
    const float* p1 = xb + (size_t)row * Cdim;
    const float* p2 = y  + (size_t)row * Cdim;
    float v[4]; float s = 0.f, s2 = 0.f;
#pragma unroll
    for (int i = 0; i < 4; i++) {
        int idx = tid + i * 256;
        v[i] = p1[idx] + p2[idx];
        s += v[i]; s2 += v[i] * v[i];
    }
#pragma unroll
    for (int o = 16; o; o >>= 1) {
        s  += __shfl_xor_sync(0xffffffffu, s,  o);
        s2 += __shfl_xor_sync(0xffffffffu, s2, o);
    }
    if ((tid & 31) == 0) { red[tid >> 5] = s; red[(tid >> 5) + 8] = s2; }
    __syncthreads();
    float S = 0.f, S2 = 0.f;
#pragma unroll
    for (int w = 0; w < 8; w++) { S += red[w]; S2 += red[w + 8]; }
    float mean = S * (1.f / Cdim);
    float var  = S2 * (1.f / Cdim) - mean * mean;
    float rs   = rsqrtf(var + 1e-5f);
#pragma unroll
    for (int i = 0; i < 4; i++) {
        int idx = tid + i * 256;
        out[(size_t)row * Cdim + idx] = (v[i] - mean) * rs * gam[idx] + bet[idx];
    }
}

// ---------------- causal flash attention, fp32, 64x64 tiles --------------
#define FPAD 68
__global__ __launch_bounds__(256)
void flash_kernel(const float* __restrict__ q, const float* __restrict__ k,
                  const float* __restrict__ v, const float* __restrict__ temp,
                  float* __restrict__ out)
{
    extern __shared__ float sm[];
    float* Qt   = sm;
    float* Kt   = Qt + 64 * FPAD;
    float* Vs   = Kt + 64 * FPAD;
    float* St   = Vs + 64 * FPAD;
    float* mrow = St + 64 * FPAD;
    float* lrow = mrow + 64;
    float* arow = lrow + 64;

    const int tid = threadIdx.x;
    const int qt = blockIdx.x, h = blockIdx.y, b = blockIdx.z;
    const int bh = b * Hdim + h;
    const float* qb = q + ((size_t)bh * Tdim + qt * 64) * HDdim;
    const float* kb = k + (size_t)bh * Tdim * HDdim;
    const float* vb = v + (size_t)bh * Tdim * HDdim;

    float tv = temp[h];
    float sp = (tv > 20.f) ? tv : log1pf(expf(tv));
    float sc = sp * (1.4426950408889634f / 8.0f);

    {
        int r  = tid >> 2;
        int d4 = (tid & 3) * 16;
#pragma unroll
        for (int u = 0; u < 4; u++) {
            float4 qv = *(const float4*)(qb + r * 64 + d4 + u * 4);
            Qt[(d4 + u*4 + 0) * FPAD + r] = qv.x * sc;
            Qt[(d4 + u*4 + 1) * FPAD + r] = qv.y * sc;
            Qt[(d4 + u*4 + 2) * FPAD + r] = qv.z * sc;
            Qt[(d4 + u*4 + 3) * FPAD + r] = qv.w * sc;
        }
    }
    if (tid < 64) { mrow[tid] = -1e30f; lrow[tid] = 0.f; }

    const int tr = (tid >> 4) * 4;
    const int tc = (tid & 15) * 4;
    float o[4][4] = {};

    for (int j = 0; j <= qt; j++) {
        __syncthreads();
        {
            int r  = tid >> 2;
            int d4 = (tid & 3) * 16;
            const float* kr = kb + ((size_t)j * 64 + r) * 64 + d4;
            const float* vr = vb + ((size_t)j * 64 + r) * 64 + d4;
#pragma unroll
            for (int u = 0; u < 4; u++) {
                float4 k4 = *(const float4*)(kr + u * 4);
                Kt[(d4 + u*4 + 0) * FPAD + r] = k4.x;
                Kt[(d4 + u*4 + 1) * FPAD + r] = k4.y;
                Kt[(d4 + u*4 + 2) * FPAD + r] = k4.z;
                Kt[(d4 + u*4 + 3) * FPAD + r] = k4.w;
                *(float4*)&Vs[r * FPAD + d4 + u * 4] = *(const float4*)(vr + u * 4);
            }
        }
        __syncthreads();

        float sacc[4][4] = {};
#pragma unroll 8
        for (int kk = 0; kk < 64; kk++) {
            float4 qv = *(const float4*)&Qt[kk * FPAD + tr];
            float4 kv4 = *(const float4*)&Kt[kk * FPAD + tc];
            float qa[4] = {qv.x, qv.y, qv.z, qv.w};
            float ka[4] = {kv4.x, kv4.y, kv4.z, kv4.w};
#pragma unroll
            for (int i = 0; i < 4; i++)
#pragma unroll
                for (int jj = 0; jj < 4; jj++)
                    sacc[i][jj] = fmaf(qa[i], ka[jj], sacc[i][jj]);
        }
        const bool diag = (j == qt);
#pragma unroll
        for (int i = 0; i < 4; i++)
#pragma unroll
            for (int jj = 0; jj < 4; jj++) {
                float val = sacc[i][jj];
                if (diag && (tc + jj > tr + i)) val = -1e30f;
                St[(tc + jj) * FPAD + (tr + i)] = val;
            }
        __syncthreads();

        {
            int row = tid >> 2, seg = tid & 3;
            float mx = -1e30f;
#pragma unroll
            for (int i = 0; i < 16; i++)
                mx = fmaxf(mx, St[(seg * 16 + i) * FPAD + row]);
            mx = fmaxf(mx, __shfl_xor_sync(0xffffffffu, mx, 1));
            mx = fmaxf(mx, __shfl_xor_sync(0xffffffffu, mx, 2));
            float mold = mrow[row];
            float mnew = fmaxf(mold, mx);
            float al   = exp2f(mold - mnew);
            float ssum = 0.f;
#pragma unroll
            for (int i = 0; i < 16; i++) {
                float p = exp2f(St[(seg * 16 + i) * FPAD + row] - mnew);
                St[(seg * 16 + i) * FPAD + row] = p;
                ssum += p;
            }
            ssum += __shfl_xor_sync(0xffffffffu, ssum, 1);
            ssum += __shfl_xor_sync(0xffffffffu, ssum, 2);
            if (seg == 0) {
                mrow[row] = mnew;
                arow[row] = al;
                lrow[row] = lrow[row] * al + ssum;
            }
        }
        __syncthreads();

#pragma unroll
        for (int i = 0; i < 4; i++) {
            float al = arow[tr + i];
#pragma unroll
            for (int jj = 0; jj < 4; jj++) o[i][jj] *= al;
        }
#pragma unroll 8
        for (int kk = 0; kk < 64; kk++) {
            float4 pv = *(const float4*)&St[kk * FPAD + tr];
            float4 vv4 = *(const float4*)&Vs[kk * FPAD + tc];
            float pa[4] = {pv.x, pv.y, pv.z, pv.w};
            float va[4] = {vv4.x, vv4.y, vv4.z, vv4.w};
#pragma unroll
            for (int i = 0; i < 4; i++)
#pragma unroll
                for (int jj = 0; jj < 4; jj++)
                    o[i][jj] = fmaf(pa[i], va[jj], o[i][jj]);
        }
    }

#pragma unroll
    for (int i = 0; i < 4; i++) {
        int r = tr + i;
        float linv = 1.0f / lrow[r];
        float4 vo;
        vo.x = o[i][0] * linv; vo.y = o[i][1] * linv;
        vo.z = o[i][2] * linv; vo.w = o[i][3] * linv;
        size_t dst = ((size_t)b * Tdim + (size_t)qt * 64 + r) * Cdim + h * HDdim + tc;
        *(float4*)(out + dst) = vo;
    }
}

// ---------------- host ----------------
static float* symaddr(const void* s) {
    void* p = nullptr;
    cudaGetSymbolAddress(&p, s);
    return (float*)p;
}

extern "C" void kernel_launch(void* const* d_in, const int* in_sizes, int n_in,
                              void* d_out, int out_size)
{
    const float* x     = (const float*)d_in[0];
    const float* A_log = (const float*)d_in[1];
    const float* Wd    = (const float*)d_in[2];
    const float* bd    = (const float*)d_in[3];
    const float* WB    = (const float*)d_in[4];
    const float* WC    = (const float*)d_in[5];
    const float* Wq    = (const float*)d_in[6];
    const float* bq    = (const float*)d_in[7];
    const float* Wk    = (const float*)d_in[8];
    const float* bk    = (const float*)d_in[9];
    const float* Wv    = (const float*)d_in[10];
    const float* bv    = (const float*)d_in[11];
    const float* Wx    = (const float*)d_in[12];
    const float* bx    = (const float*)d_in[13];
    const float* Wo    = (const float*)d_in[14];
    const float* bo    = (const float*)d_in[15];
    const float* lng   = (const float*)d_in[16];
    const float* lnb   = (const float*)d_in[17];
    const float* temp  = (const float*)d_in[18];
    float* out = (float*)d_out;

    float* xbase = symaddr(g_xbase);
    float* delta = symaddr(g_delta);
    float* Bm    = symaddr(g_Bmat);
    float* Cm    = symaddr(g_Cmat);
    float* y     = symaddr(g_y);
    float* cumD  = symaddr(g_cumD);
    float* hend  = symaddr(g_hend);
    float* hin   = symaddr(g_hin);
    float* hyb   = symaddr(g_hyb);
    float* q     = symaddr(g_q);
    float* k     = symaddr(g_k);
    float* v     = symaddr(g_v);
    float* ao    = symaddr(g_ao);

    dim3 gg(Cdim / 128, Mrows / 128);   // (8, 32)

    tgemm_kernel<0><<<gg, 256>>>(x, Wx, bx, xbase, Mrows, Cdim, Cdim);
    tgemm_kernel<1><<<gg, 256>>>(x, Wd, bd, delta, Mrows, Cdim, Cdim);
    skinny_kernel<<<Mrows / 16, 256>>>(x, WB, WC, Bm, Cm);

    scanA_kernel<<<dim3(Cdim / 16, NCH, Bdim), 256>>>(A_log, delta, xbase, Bm, Cm, y, cumD, hend);
    scanB_kernel<<<(Bdim * Cdim * Sdim) / 256, 256>>>(A_log, cumD, hend, hin);
    scanC_kernel<<<dim3(Cdim / 16, Tdim / 16, Bdim), 256>>>(A_log, Cm, hin, cumD, y);

    addln_kernel<<<Mrows, 256>>>(xbase, y, lng, lnb, hyb);
    tgemm_kernel<2><<<gg, 256>>>(hyb, Wq, bq, q, Mrows, Cdim, Cdim);
    tgemm_kernel<2><<<gg, 256>>>(hyb, Wk, bk, k, Mrows, Cdim, Cdim);
    tgemm_kernel<2><<<gg, 256>>>(hyb, Wv, bv, v, Mrows, Cdim, Cdim);

    const int flash_smem = (4 * 64 * FPAD + 3 * 64) * (int)sizeof(float);
    cudaFuncSetAttribute(flash_kernel, cudaFuncAttributeMaxDynamicSharedMemorySize, flash_smem);
    flash_kernel<<<dim3(Tdim / 64, Hdim, Bdim), 256, flash_smem>>>(q, k, v, temp, ao);

    tgemm_kernel<0><<<gg, 256>>>(ao, Wo, bo, out, Mrows, Cdim, Cdim);
}

// round 5
// speedup vs baseline: 1.4562x; 1.2082x over previous
#include <cuda_runtime.h>
#include <cuda_bf16.h>
#include <math.h>
#include <stdint.h>

#define Bdim 2
#define Tdim 2048
#define Cdim 1024
#define Hdim 16
#define Sdim 16
#define HDdim 64
#define Mrows (Bdim*Tdim)   /* 4096 */
#define NCH 16              /* scan chunks */
#define CHT (Tdim/NCH)      /* 128 t per chunk */
#define WSZ (Cdim*Cdim)

// ---------------- device scratch (static, no allocation) ----------------
__device__ float g_xbase[Mrows*Cdim];
__device__ float g_delta[Mrows*Cdim];
__device__ float g_Bmat [Mrows*Sdim];
__device__ float g_Cmat [Mrows*Sdim];
__device__ float g_y    [Mrows*Cdim];
__device__ float g_cumD [Mrows*Cdim];
__device__ float g_hend [Bdim*NCH*Cdim*Sdim];
__device__ float g_hin  [Bdim*NCH*Cdim*Sdim];
__device__ float g_hyb  [Mrows*Cdim];
__device__ float g_q    [Mrows*Cdim];
__device__ float g_k    [Mrows*Cdim];
__device__ float g_v    [Mrows*Cdim];
__device__ float g_ao   [Mrows*Cdim];
__device__ __nv_bfloat16 g_ahi[Mrows*Cdim];
__device__ __nv_bfloat16 g_alo[Mrows*Cdim];
__device__ __nv_bfloat16 g_whi[6*WSZ];
__device__ __nv_bfloat16 g_wlo[6*WSZ];

// ---------------- bf16 mma helper ----------------
__device__ __forceinline__ void mma_bf16(float* d, const uint32_t* a, const uint32_t* b) {
    asm volatile(
        "mma.sync.aligned.m16n8k16.row.col.f32.bf16.bf16.f32 "
        "{%0,%1,%2,%3}, {%4,%5,%6,%7}, {%8,%9}, {%0,%1,%2,%3};"
        : "+f"(d[0]), "+f"(d[1]), "+f"(d[2]), "+f"(d[3])
        : "r"(a[0]), "r"(a[1]), "r"(a[2]), "r"(a[3]), "r"(b[0]), "r"(b[1]));
}

// ---------------- conversion kernels ----------------
__global__ __launch_bounds__(256)
void actconv_kernel(const float* __restrict__ src,
                    __nv_bfloat16* __restrict__ hi, __nv_bfloat16* __restrict__ lo)
{
    size_t i = ((size_t)blockIdx.x * 256 + threadIdx.x) * 4;
    float4 v = *(const float4*)(src + i);
    __nv_bfloat16 h0 = __float2bfloat16_rn(v.x);
    __nv_bfloat16 h1 = __float2bfloat16_rn(v.y);
    __nv_bfloat16 h2 = __float2bfloat16_rn(v.z);
    __nv_bfloat16 h3 = __float2bfloat16_rn(v.w);
    __nv_bfloat16 l0 = __float2bfloat16_rn(v.x - __bfloat162float(h0));
    __nv_bfloat16 l1 = __float2bfloat16_rn(v.y - __bfloat162float(h1));
    __nv_bfloat16 l2 = __float2bfloat16_rn(v.z - __bfloat162float(h2));
    __nv_bfloat16 l3 = __float2bfloat16_rn(v.w - __bfloat162float(h3));
    ushort4 uh, ul;
    uh.x = __bfloat16_as_ushort(h0); uh.y = __bfloat16_as_ushort(h1);
    uh.z = __bfloat16_as_ushort(h2); uh.w = __bfloat16_as_ushort(h3);
    ul.x = __bfloat16_as_ushort(l0); ul.y = __bfloat16_as_ushort(l1);
    ul.z = __bfloat16_as_ushort(l2); ul.w = __bfloat16_as_ushort(l3);
    *(ushort4*)(hi + i) = uh;
    *(ushort4*)(lo + i) = ul;
}

// W [K][N] -> Wt hi/lo [N][K] (transposed)
__global__ __launch_bounds__(256)
void wconv_kernel(const float* __restrict__ W,
                  __nv_bfloat16* __restrict__ whi, __nv_bfloat16* __restrict__ wlo)
{
    __shared__ float ts[32][33];
    const int tid = threadIdx.x;
    const int tx = tid & 31, ty = tid >> 5;
    const int n0 = blockIdx.x * 32, k0 = blockIdx.y * 32;
#pragma unroll
    for (int i = 0; i < 4; i++)
        ts[ty + 8 * i][tx] = W[(size_t)(k0 + ty + 8 * i) * Cdim + n0 + tx];
    __syncthreads();
#pragma unroll
    for (int i = 0; i < 4; i++) {
        int r = ty + 8 * i;
        float x = ts[tx][r];
        __nv_bfloat16 h = __float2bfloat16_rn(x);
        __nv_bfloat16 l = __float2bfloat16_rn(x - __bfloat162float(h));
        size_t o = (size_t)(n0 + r) * Cdim + k0 + tx;
        whi[o] = h;
        wlo[o] = l;
    }
}

// ---------------- bf16 split tensor GEMM: out = act(A @ W + bias) --------
// Ahi/Alo: [M][K] bf16 row-major. Whi/Wlo: [N][K] bf16 row-major (pre-transposed).
// BM=BN=128, BK=32, 256 threads = 8 warps (2m x 4n), warp tile 64x32.
// D = AhiBhi + AloBhi + AhiBlo  (3 HMMA passes fused in k-loop).
#define SPITCH 40   /* bf16 row stride: banks (20r+c) conflict-free */
template<int MODE>
__global__ __launch_bounds__(256)
void bgemm_kernel(const __nv_bfloat16* __restrict__ Ahi, const __nv_bfloat16* __restrict__ Alo,
                  const __nv_bfloat16* __restrict__ Whi, const __nv_bfloat16* __restrict__ Wlo,
                  const float* __restrict__ bias, float* __restrict__ out)
{
    __shared__ __nv_bfloat16 Ah[128 * SPITCH];
    __shared__ __nv_bfloat16 Al[128 * SPITCH];
    __shared__ __nv_bfloat16 Bh[128 * SPITCH];
    __shared__ __nv_bfloat16 Bl[128 * SPITCH];

    const int tid  = threadIdx.x;
    const int lane = tid & 31;
    const int warp = tid >> 5;
    const int wm   = (warp >> 2) * 64;
    const int wn   = (warp & 3) * 32;
    const int gr   = lane >> 2;
    const int ctid = lane & 3;
    const int c2   = ctid * 2;
    const int row0 = blockIdx.y * 128;
    const int col0 = blockIdx.x * 128;

    float acc[4][4][4];
#pragma unroll
    for (int i = 0; i < 4; i++)
#pragma unroll
        for (int j = 0; j < 4; j++)
#pragma unroll
            for (int e = 0; e < 4; e++) acc[i][j][e] = 0.f;

    const int lrow = tid >> 1;        // 0..127
    const int lseg = (tid & 1) * 16;  // 0 or 16

    uint4 pah[2], pal[2], pbh[2], pbl[2];
    {
        size_t gA = (size_t)(row0 + lrow) * Cdim + lseg;
        size_t gB = (size_t)(col0 + lrow) * Cdim + lseg;
        pah[0] = *(const uint4*)(Ahi + gA); pah[1] = *(const uint4*)(Ahi + gA + 8);
        pal[0] = *(const uint4*)(Alo + gA); pal[1] = *(const uint4*)(Alo + gA + 8);
        pbh[0] = *(const uint4*)(Whi + gB); pbh[1] = *(const uint4*)(Whi + gB + 8);
        pbl[0] = *(const uint4*)(Wlo + gB); pbl[1] = *(const uint4*)(Wlo + gB + 8);
    }

    for (int k0 = 0; k0 < Cdim; k0 += 32) {
        __syncthreads();
        {
            int so = lrow * SPITCH + lseg;
            *(uint4*)&Ah[so]     = pah[0]; *(uint4*)&Ah[so + 8] = pah[1];
            *(uint4*)&Al[so]     = pal[0]; *(uint4*)&Al[so + 8] = pal[1];
            *(uint4*)&Bh[so]     = pbh[0]; *(uint4*)&Bh[so + 8] = pbh[1];
            *(uint4*)&Bl[so]     = pbl[0]; *(uint4*)&Bl[so + 8] = pbl[1];
        }
        __syncthreads();

        if (k0 + 32 < Cdim) {
            size_t gA = (size_t)(row0 + lrow) * Cdim + k0 + 32 + lseg;
            size_t gB = (size_t)(col0 + lrow) * Cdim + k0 + 32 + lseg;
            pah[0] = *(const uint4*)(Ahi + gA); pah[1] = *(const uint4*)(Ahi + gA + 8);
            pal[0] = *(const uint4*)(Alo + gA); pal[1] = *(const uint4*)(Alo + gA + 8);
            pbh[0] = *(const uint4*)(Whi + gB); pbh[1] = *(const uint4*)(Whi + gB + 8);
            pbl[0] = *(const uint4*)(Wlo + gB); pbl[1] = *(const uint4*)(Wlo + gB + 8);
        }

#pragma unroll
        for (int ks = 0; ks < 2; ks++) {
            const int kk = ks * 16 + c2;
            uint32_t ahf[4][4], alf[4][4];
#pragma unroll
            for (int mt = 0; mt < 4; mt++) {
                int m = (wm + mt * 16 + gr) * SPITCH + kk;
                ahf[mt][0] = *(const uint32_t*)&Ah[m];
                ahf[mt][1] = *(const uint32_t*)&Ah[m + 8 * SPITCH];
                ahf[mt][2] = *(const uint32_t*)&Ah[m + 8];
                ahf[mt][3] = *(const uint32_t*)&Ah[m + 8 * SPITCH + 8];
                alf[mt][0] = *(const uint32_t*)&Al[m];
                alf[mt][1] = *(const uint32_t*)&Al[m + 8 * SPITCH];
                alf[mt][2] = *(const uint32_t*)&Al[m + 8];
                alf[mt][3] = *(const uint32_t*)&Al[m + 8 * SPITCH + 8];
            }
            uint32_t bhf[4][2], blf[4][2];
#pragma unroll
            for (int nt = 0; nt < 4; nt++) {
                int n = (wn + nt * 8 + gr) * SPITCH + kk;
                bhf[nt][0] = *(const uint32_t*)&Bh[n];
                bhf[nt][1] = *(const uint32_t*)&Bh[n + 8];
                blf[nt][0] = *(const uint32_t*)&Bl[n];
                blf[nt][1] = *(const uint32_t*)&Bl[n + 8];
            }
#pragma unroll
            for (int mt = 0; mt < 4; mt++)
#pragma unroll
                for (int nt = 0; nt < 4; nt++) {
                    mma_bf16(acc[mt][nt], ahf[mt], bhf[nt]);
                    mma_bf16(acc[mt][nt], alf[mt], bhf[nt]);
                    mma_bf16(acc[mt][nt], ahf[mt], blf[nt]);
                }
        }
    }

    // epilogue
#pragma unroll
    for (int mt = 0; mt < 4; mt++) {
#pragma unroll
        for (int nt = 0; nt < 4; nt++) {
            int c = col0 + wn + nt * 8 + c2;
            float2 bb = *(const float2*)(bias + c);
#pragma unroll
            for (int half = 0; half < 2; half++) {
                int r = row0 + wm + mt * 16 + gr + half * 8;
                float vx = acc[mt][nt][half * 2 + 0] + bb.x;
                float vy = acc[mt][nt][half * 2 + 1] + bb.y;
                if (MODE == 1) {
                    vx = (vx > 20.f) ? vx : log1pf(expf(vx));
                    vy = (vy > 20.f) ? vy : log1pf(expf(vy));
                }
                float2 vv = make_float2(vx, vy);
                if (MODE == 2) {
                    int b = r >> 11, t = r & (Tdim - 1);
                    int h = c >> 6, d = c & 63;
                    float* dst = out + (((size_t)(b * Hdim + h) * Tdim + t) << 6) + d;
                    *(float2*)dst = vv;
                } else {
                    *(float2*)(out + (size_t)r * Cdim + c) = vv;
                }
            }
        }
    }
}

// ---------------- skinny GEMM: Bm = x@WB, Cm = x@WC (N=16) ----------------
__global__ __launch_bounds__(256)
void skinny_kernel(const float* __restrict__ x, const float* __restrict__ WB,
                   const float* __restrict__ WC,
                   float* __restrict__ Bm, float* __restrict__ Cm)
{
    __shared__ float wb[128 * 16];
    __shared__ float wc[128 * 16];
    __shared__ float xs[16][128];
    const int tid = threadIdx.x;
    const int m0  = blockIdx.x * 16;
    const int rl  = tid >> 4;
    const int s   = tid & 15;
    float accB = 0.f, accC = 0.f;

    for (int k0 = 0; k0 < Cdim; k0 += 128) {
#pragma unroll
        for (int u = 0; u < 2; u++) {
            int idx = tid * 8 + u * 4;
            *(float4*)&wb[idx] = *(const float4*)(WB + k0 * 16 + idx);
            *(float4*)&wc[idx] = *(const float4*)(WC + k0 * 16 + idx);
        }
        {
            int row = tid >> 4;
            int cc  = (tid & 15) * 8;
            const float* xp = x + (size_t)(m0 + row) * Cdim + k0 + cc;
            *(float4*)&xs[row][cc]     = *(const float4*)(xp);
            *(float4*)&xs[row][cc + 4] = *(const float4*)(xp + 4);
        }
        __syncthreads();
#pragma unroll 8
        for (int kk = 0; kk < 128; kk++) {
            float xv = xs[rl][kk];
            accB = fmaf(xv, wb[kk * 16 + s], accB);
            accC = fmaf(xv, wc[kk * 16 + s], accC);
        }
        __syncthreads();
    }
    Bm[(size_t)(m0 + rl) * 16 + s] = accB;
    Cm[(size_t)(m0 + rl) * 16 + s] = accC;
}

// ================= chunked SSM scan =================
#define TTA 32
__global__ __launch_bounds__(256)
void scanA_kernel(const float* __restrict__ A_log,
                  const float* __restrict__ delta,
                  const float* __restrict__ xb,
                  const float* __restrict__ Bm,
                  const float* __restrict__ Cm,
                  float* __restrict__ ylocal,
                  float* __restrict__ cumD,
                  float* __restrict__ hend)
{
    __shared__ float2 sdx[TTA][16];
    __shared__ float2 sbc[TTA][16];

    const int tid = threadIdx.x;
    const int s   = tid & 15;
    const int cl  = tid >> 4;
    const int c0  = blockIdx.x * 16;
    const int ch  = blockIdx.y;
    const int b   = blockIdx.z;
    const int c   = c0 + cl;
    const int t00 = ch * CHT;
    const float LOG2E = 1.4426950408889634f;
    const float a2 = -expf(A_log[c * Sdim + s]) * LOG2E;

    float h = 0.f, cum = 0.f;

    for (int t0 = t00; t0 < t00 + CHT; t0 += TTA) {
        __syncthreads();
#pragma unroll
        for (int u = 0; u < 2; u++) {
            int e = tid + u * 256;
            int tt = e >> 4, cc = e & 15;
            size_t g = ((size_t)b * Tdim + t0 + tt) * Cdim + c0 + cc;
            sdx[tt][cc] = make_float2(delta[g], xb[g]);
        }
#pragma unroll
        for (int u = 0; u < 2; u++) {
            int e = tid + u * 256;
            int tt = e >> 4, ss = e & 15;
            size_t g = ((size_t)b * Tdim + t0 + tt) * Sdim + ss;
            sbc[tt][ss] = make_float2(Bm[g], Cm[g]);
        }
        __syncthreads();

#pragma unroll
        for (int tt = 0; tt < TTA; tt++) {
            float2 dx = sdx[tt][cl];
            float2 bc = sbc[tt][s];
            cum += dx.x;
            float e = exp2f(dx.x * a2);
            h = fmaf(e, h, dx.x * dx.y * bc.x);
            float p = h * bc.y;
            p += __shfl_xor_sync(0xffffffffu, p, 8);
            p += __shfl_xor_sync(0xffffffffu, p, 4);
            p += __shfl_xor_sync(0xffffffffu, p, 2);
            p += __shfl_xor_sync(0xffffffffu, p, 1);
            if (s == 0) {
                size_t g = ((size_t)b * Tdim + t0 + tt) * Cdim + c;
                ylocal[g] = p;
                cumD[g]   = cum;
            }
        }
    }
    hend[(((size_t)b * NCH + ch) * Cdim + c) * Sdim + s] = h;
}

__global__ __launch_bounds__(256)
void scanB_kernel(const float* __restrict__ A_log,
                  const float* __restrict__ cumD,
                  const float* __restrict__ hend,
                  float* __restrict__ hin)
{
    const int gid = blockIdx.x * 256 + threadIdx.x;
    const int s = gid & 15;
    const int c = (gid >> 4) & (Cdim - 1);
    const int b = gid >> 14;
    const float LOG2E = 1.4426950408889634f;
    const float a2 = -expf(A_log[c * Sdim + s]) * LOG2E;

    float h = 0.f;
#pragma unroll
    for (int k = 0; k < NCH; k++) {
        size_t idx = (((size_t)b * NCH + k) * Cdim + c) * Sdim + s;
        hin[idx] = h;
        float sd = cumD[((size_t)b * Tdim + k * CHT + CHT - 1) * Cdim + c];
        h = fmaf(exp2f(a2 * sd), h, hend[idx]);
    }
}

__global__ __launch_bounds__(256)
void scanC_kernel(const float* __restrict__ A_log,
                  const float* __restrict__ Cm,
                  const float* __restrict__ hin,
                  const float* __restrict__ cumD,
                  float* __restrict__ y)
{
    __shared__ float a2s[16][17];
    __shared__ float hns[16][17];
    __shared__ float cts[16][16];

    const int tid = threadIdx.x;
    const int c0  = blockIdx.x * 16;
    const int t0  = blockIdx.y * 16;
    const int b   = blockIdx.z;
    const int ch  = t0 / CHT;
    const float LOG2E = 1.4426950408889634f;

    {
        int i = tid >> 4, j = tid & 15;
        a2s[i][j] = -expf(A_log[(c0 + i) * Sdim + j]) * LOG2E;
        hns[i][j] = hin[(((size_t)b * NCH + ch) * Cdim + c0 + i) * Sdim + j];
        cts[i][j] = Cm[((size_t)b * Tdim + t0 + i) * Sdim + j];
    }
    __syncthreads();

    const int tl = tid >> 4;
    const int cl = tid & 15;
    size_t g = ((size_t)b * Tdim + t0 + tl) * Cdim + c0 + cl;
    float cd  = cumD[g];
    float acc = y[g];
#pragma unroll
    for (int s = 0; s < 16; s++)
        acc = fmaf(cts[tl][s] * hns[cl][s], exp2f(a2s[cl][s] * cd), acc);
    y[g] = acc;
}

// ---------------- add + LayerNorm ----------------
__global__ __launch_bounds__(256)
void addln_kernel(const float* __restrict__ xb, const float* __restrict__ y,
                  const float* __restrict__ gam, const float* __restrict__ bet,
                  float* __restrict__ out)
{
    __shared__ float red[16];
    const int row = blockIdx.x, tid = threadIdx.x;
    const float* p1 = xb + (size_t)row * Cdim;
    const float* p2 = y  + (size_t)row * Cdim;
    float v[4]; float s = 0.f, s2 = 0.f;
#pragma unroll
    for (int i = 0; i < 4; i++) {
        int idx = tid + i * 256;
        v[i] = p1[idx] + p2[idx];
        s += v[i]; s2 += v[i] * v[i];
    }
#pragma unroll
    for (int o = 16; o; o >>= 1) {
        s  += __shfl_xor_sync(0xffffffffu, s,  o);
        s2 += __shfl_xor_sync(0xffffffffu, s2, o);
    }
    if ((tid & 31) == 0) { red[tid >> 5] = s; red[(tid >> 5) + 8] = s2; }
    __syncthreads();
    float S = 0.f, S2 = 0.f;
#pragma unroll
    for (int w = 0; w < 8; w++) { S += red[w]; S2 += red[w + 8]; }
    float mean = S * (1.f / Cdim);
    float var  = S2 * (1.f / Cdim) - mean * mean;
    float rs   = rsqrtf(var + 1e-5f);
#pragma unroll
    for (int i = 0; i < 4; i++) {
        int idx = tid + i * 256;
        out[(size_t)row * Cdim + idx] = (v[i] - mean) * rs * gam[idx] + bet[idx];
    }
}

// ---------------- causal flash attention, fp32, 64x64 tiles --------------
#define FPAD 68
__global__ __launch_bounds__(256)
void flash_kernel(const float* __restrict__ q, const float* __restrict__ k,
                  const float* __restrict__ v, const float* __restrict__ temp,
                  float* __restrict__ out)
{
    extern __shared__ float sm[];
    float* Qt   = sm;
    float* Kt   = Qt + 64 * FPAD;
    float* Vs   = Kt + 64 * FPAD;
    float* St   = Vs + 64 * FPAD;
    float* mrow = St + 64 * FPAD;
    float* lrow = mrow + 64;
    float* arow = lrow + 64;

    const int tid = threadIdx.x;
    const int qt = blockIdx.x, h = blockIdx.y, b = blockIdx.z;
    const int bh = b * Hdim + h;
    const float* qb = q + ((size_t)bh * Tdim + qt * 64) * HDdim;
    const float* kb = k + (size_t)bh * Tdim * HDdim;
    const float* vb = v + (size_t)bh * Tdim * HDdim;

    float tv = temp[h];
    float sp = (tv > 20.f) ? tv : log1pf(expf(tv));
    float sc = sp * (1.4426950408889634f / 8.0f);

    {
        int r  = tid >> 2;
        int d4 = (tid & 3) * 16;
#pragma unroll
        for (int u = 0; u < 4; u++) {
            float4 qv = *(const float4*)(qb + r * 64 + d4 + u * 4);
            Qt[(d4 + u*4 + 0) * FPAD + r] = qv.x * sc;
            Qt[(d4 + u*4 + 1) * FPAD + r] = qv.y * sc;
            Qt[(d4 + u*4 + 2) * FPAD + r] = qv.z * sc;
            Qt[(d4 + u*4 + 3) * FPAD + r] = qv.w * sc;
        }
    }
    if (tid < 64) { mrow[tid] = -1e30f; lrow[tid] = 0.f; }

    const int tr = (tid >> 4) * 4;
    const int tc = (tid & 15) * 4;
    float o[4][4] = {};

    for (int j = 0; j <= qt; j++) {
        __syncthreads();
        {
            int r  = tid >> 2;
            int d4 = (tid & 3) * 16;
            const float* kr = kb + ((size_t)j * 64 + r) * 64 + d4;
            const float* vr = vb + ((size_t)j * 64 + r) * 64 + d4;
#pragma unroll
            for (int u = 0; u < 4; u++) {
                float4 k4 = *(const float4*)(kr + u * 4);
                Kt[(d4 + u*4 + 0) * FPAD + r] = k4.x;
                Kt[(d4 + u*4 + 1) * FPAD + r] = k4.y;
                Kt[(d4 + u*4 + 2) * FPAD + r] = k4.z;
                Kt[(d4 + u*4 + 3) * FPAD + r] = k4.w;
                *(float4*)&Vs[r * FPAD + d4 + u * 4] = *(const float4*)(vr + u * 4);
            }
        }
        __syncthreads();

        float sacc[4][4] = {};
#pragma unroll 8
        for (int kk = 0; kk < 64; kk++) {
            float4 qv = *(const float4*)&Qt[kk * FPAD + tr];
            float4 kv4 = *(const float4*)&Kt[kk * FPAD + tc];
            float qa[4] = {qv.x, qv.y, qv.z, qv.w};
            float ka[4] = {kv4.x, kv4.y, kv4.z, kv4.w};
#pragma unroll
            for (int i = 0; i < 4; i++)
#pragma unroll
                for (int jj = 0; jj < 4; jj++)
                    sacc[i][jj] = fmaf(qa[i], ka[jj], sacc[i][jj]);
        }
        const bool diag = (j == qt);
#pragma unroll
        for (int i = 0; i < 4; i++)
#pragma unroll
            for (int jj = 0; jj < 4; jj++) {
                float val = sacc[i][jj];
                if (diag && (tc + jj > tr + i)) val = -1e30f;
                St[(tc + jj) * FPAD + (tr + i)] = val;
            }
        __syncthreads();

        {
            int row = tid >> 2, seg = tid & 3;
            float mx = -1e30f;
#pragma unroll
            for (int i = 0; i < 16; i++)
                mx = fmaxf(mx, St[(seg * 16 + i) * FPAD + row]);
            mx = fmaxf(mx, __shfl_xor_sync(0xffffffffu, mx, 1));
            mx = fmaxf(mx, __shfl_xor_sync(0xffffffffu, mx, 2));
            float mold = mrow[row];
            float mnew = fmaxf(mold, mx);
            float al   = exp2f(mold - mnew);
            float ssum = 0.f;
#pragma unroll
            for (int i = 0; i < 16; i++) {
                float p = exp2f(St[(seg * 16 + i) * FPAD + row] - mnew);
                St[(seg * 16 + i) * FPAD + row] = p;
                ssum += p;
            }
            ssum += __shfl_xor_sync(0xffffffffu, ssum, 1);
            ssum += __shfl_xor_sync(0xffffffffu, ssum, 2);
            if (seg == 0) {
                mrow[row] = mnew;
                arow[row] = al;
                lrow[row] = lrow[row] * al + ssum;
            }
        }
        __syncthreads();

#pragma unroll
        for (int i = 0; i < 4; i++) {
            float al = arow[tr + i];
#pragma unroll
            for (int jj = 0; jj < 4; jj++) o[i][jj] *= al;
        }
#pragma unroll 8
        for (int kk = 0; kk < 64; kk++) {
            float4 pv = *(const float4*)&St[kk * FPAD + tr];
            float4 vv4 = *(const float4*)&Vs[kk * FPAD + tc];
            float pa[4] = {pv.x, pv.y, pv.z, pv.w};
            float va[4] = {vv4.x, vv4.y, vv4.z, vv4.w};
#pragma unroll
            for (int i = 0; i < 4; i++)
#pragma unroll
                for (int jj = 0; jj < 4; jj++)
                    o[i][jj] = fmaf(pa[i], va[jj], o[i][jj]);
        }
    }

#pragma unroll
    for (int i = 0; i < 4; i++) {
        int r = tr + i;
        float linv = 1.0f / lrow[r];
        float4 vo;
        vo.x = o[i][0] * linv; vo.y = o[i][1] * linv;
        vo.z = o[i][2] * linv; vo.w = o[i][3] * linv;
        size_t dst = ((size_t)b * Tdim + (size_t)qt * 64 + r) * Cdim + h * HDdim + tc;
        *(float4*)(out + dst) = vo;
    }
}

// ---------------- host ----------------
static float* symaddr(const void* s) {
    void* p = nullptr;
    cudaGetSymbolAddress(&p, s);
    return (float*)p;
}
static __nv_bfloat16* symaddr_bf(const void* s) {
    void* p = nullptr;
    cudaGetSymbolAddress(&p, s);
    return (__nv_bfloat16*)p;
}

extern "C" void kernel_launch(void* const* d_in, const int* in_sizes, int n_in,
                              void* d_out, int out_size)
{
    const float* x     = (const float*)d_in[0];
    const float* A_log = (const float*)d_in[1];
    const float* Wd    = (const float*)d_in[2];
    const float* bd    = (const float*)d_in[3];
    const float* WB    = (const float*)d_in[4];
    const float* WC    = (const float*)d_in[5];
    const float* Wq    = (const float*)d_in[6];
    const float* bq    = (const float*)d_in[7];
    const float* Wk    = (const float*)d_in[8];
    const float* bk    = (const float*)d_in[9];
    const float* Wv    = (const float*)d_in[10];
    const float* bv    = (const float*)d_in[11];
    const float* Wx    = (const float*)d_in[12];
    const float* bx    = (const float*)d_in[13];
    const float* Wo    = (const float*)d_in[14];
    const float* bo    = (const float*)d_in[15];
    const float* lng   = (const float*)d_in[16];
    const float* lnb   = (const float*)d_in[17];
    const float* temp  = (const float*)d_in[18];
    float* out = (float*)d_out;

    float* xbase = symaddr(g_xbase);
    float* delta = symaddr(g_delta);
    float* Bm    = symaddr(g_Bmat);
    float* Cm    = symaddr(g_Cmat);
    float* y     = symaddr(g_y);
    float* cumD  = symaddr(g_cumD);
    float* hend  = symaddr(g_hend);
    float* hin   = symaddr(g_hin);
    float* hyb   = symaddr(g_hyb);
    float* q     = symaddr(g_q);
    float* k     = symaddr(g_k);
    float* v     = symaddr(g_v);
    float* ao    = symaddr(g_ao);
    __nv_bfloat16* ahi = symaddr_bf(g_ahi);
    __nv_bfloat16* alo = symaddr_bf(g_alo);
    __nv_bfloat16* whi = symaddr_bf(g_whi);
    __nv_bfloat16* wlo = symaddr_bf(g_wlo);

    dim3 wcg(Cdim / 32, Cdim / 32);
    wconv_kernel<<<wcg, 256>>>(Wx, whi + 0 * WSZ, wlo + 0 * WSZ);
    wconv_kernel<<<wcg, 256>>>(Wd, whi + 1 * WSZ, wlo + 1 * WSZ);
    wconv_kernel<<<wcg, 256>>>(Wq, whi + 2 * WSZ, wlo + 2 * WSZ);
    wconv_kernel<<<wcg, 256>>>(Wk, whi + 3 * WSZ, wlo + 3 * WSZ);
    wconv_kernel<<<wcg, 256>>>(Wv, whi + 4 * WSZ, wlo + 4 * WSZ);
    wconv_kernel<<<wcg, 256>>>(Wo, whi + 5 * WSZ, wlo + 5 * WSZ);

    dim3 tg(Cdim / 128, Mrows / 128);   // (8, 32)
    const int ACG = (Mrows * Cdim) / 1024;

    actconv_kernel<<<ACG, 256>>>(x, ahi, alo);
    bgemm_kernel<0><<<tg, 256>>>(ahi, alo, whi + 0 * WSZ, wlo + 0 * WSZ, bx, xbase);
    bgemm_kernel<1><<<tg, 256>>>(ahi, alo, whi + 1 * WSZ, wlo + 1 * WSZ, bd, delta);
    skinny_kernel<<<Mrows / 16, 256>>>(x, WB, WC, Bm, Cm);

    scanA_kernel<<<dim3(Cdim / 16, NCH, Bdim), 256>>>(A_log, delta, xbase, Bm, Cm, y, cumD, hend);
    scanB_kernel<<<(Bdim * Cdim * Sdim) / 256, 256>>>(A_log, cumD, hend, hin);
    scanC_kernel<<<dim3(Cdim / 16, Tdim / 16, Bdim), 256>>>(A_log, Cm, hin, cumD, y);

    addln_kernel<<<Mrows, 256>>>(xbase, y, lng, lnb, hyb);

    actconv_kernel<<<ACG, 256>>>(hyb, ahi, alo);
    bgemm_kernel<2><<<tg, 256>>>(ahi, alo, whi + 2 * WSZ, wlo + 2 * WSZ, bq, q);
    bgemm_kernel<2><<<tg, 256>>>(ahi, alo, whi + 3 * WSZ, wlo + 3 * WSZ, bk, k);
    bgemm_kernel<2><<<tg, 256>>>(ahi, alo, whi + 4 * WSZ, wlo + 4 * WSZ, bv, v);

    const int flash_smem = (4 * 64 * FPAD + 3 * 64) * (int)sizeof(float);
    cudaFuncSetAttribute(flash_kernel, cudaFuncAttributeMaxDynamicSharedMemorySize, flash_smem);
    flash_kernel<<<dim3(Tdim / 64, Hdim, Bdim), 256, flash_smem>>>(q, k, v, temp, ao);

    actconv_kernel<<<ACG, 256>>>(ao, ahi, alo);
    bgemm_kernel<0><<<tg, 256>>>(ahi, alo, whi + 5 * WSZ, wlo + 5 * WSZ, bo, out);
}